// round 4
// baseline (speedup 1.0000x reference)
#include <cuda_runtime.h>
#include <cuda_bf16.h>

// Problem constants (V,E,L,H = 128,512,8,8; B,T = 4,1024)
#define Bsz 4
#define Tt  1024
#define Vv  128
#define Ee  512
#define Hh  8
#define Ll  8
#define DH  64
#define NTOK (Bsz*Tt)          // 4096
#define QKVDIM (3*Ee)          // 1536
#define HCH (3*DH)             // 192 per-head chunk in qkv row

// ---------------- scratch (device globals; no allocation allowed) -----------
__device__ float g_x   [NTOK*Ee];
__device__ float g_qkv [NTOK*QKVDIM];
__device__ float g_att [NTOK*Ee];
__device__ float g_tmp [NTOK*Ee];
__device__ float g_aff [NTOK*Ee];
__device__ float g_out1[NTOK*Ee];
__device__ float g_logits[NTOK*Vv];
__device__ float g_partials[512];
__device__ int   g_is32;

// ---------------- helpers ----------------------------------------------------
__device__ __forceinline__ float warp_sum(float v){
#pragma unroll
    for (int o = 16; o; o >>= 1) v += __shfl_xor_sync(0xffffffffu, v, o);
    return v;
}
__device__ __forceinline__ float warp_max(float v){
#pragma unroll
    for (int o = 16; o; o >>= 1) v = fmaxf(v, __shfl_xor_sync(0xffffffffu, v, o));
    return v;
}
__device__ __forceinline__ int get_tok(const void* p, int i){
    return g_is32 ? ((const int*)p)[i] : (int)((const long long*)p)[i];
}

// int32 vs int64 token buffer detection (tokens in [0,128); if int64, every
// odd 32-bit word is 0; if int32, 64 consecutive odd words all-zero is ~impossible)
__global__ void detect_kernel(const int* __restrict__ inp){
    int is32 = 0;
    for (int i = 1; i < 128; i += 2) if (inp[i] != 0) { is32 = 1; break; }
    g_is32 = is32;
}

// ---------------- embedding --------------------------------------------------
// grid NTOK, block 128; each thread copies a float4 of the 512-wide row
__global__ void embed_kernel(const void* __restrict__ inp,
                             const float* __restrict__ emb,
                             float* __restrict__ x){
    int t = blockIdx.x;
    int tok = get_tok(inp, t);
    *(float4*)(x + (size_t)t*Ee + threadIdx.x*4) =
        *(const float4*)(emb + (size_t)tok*Ee + threadIdx.x*4);
}

// ---------------- C = A[M,K] @ W[N,K]^T + bias (opt relu) --------------------
// grid (N/64, M/64), block 256. K multiple of 16, M,N multiples of 64.
__global__ void gemm_bias_kernel(const float* __restrict__ A,
                                 const float* __restrict__ W,
                                 const float* __restrict__ bias,
                                 float* __restrict__ C,
                                 int N, int K, int doRelu){
    __shared__ float As[16][64];
    __shared__ float Ws[16][64];
    int tid = threadIdx.x;
    int rowBase = blockIdx.y * 64;
    int colBase = blockIdx.x * 64;
    int ty = tid >> 4, tx = tid & 15;
    int lr = tid >> 2;
    int lc = (tid & 3) << 2;
    float acc[4][4];
#pragma unroll
    for (int i = 0; i < 4; i++)
#pragma unroll
        for (int j = 0; j < 4; j++) acc[i][j] = 0.f;

    for (int k0 = 0; k0 < K; k0 += 16) {
        float4 a = *(const float4*)(A + (size_t)(rowBase + lr)*K + k0 + lc);
        As[lc+0][lr] = a.x; As[lc+1][lr] = a.y; As[lc+2][lr] = a.z; As[lc+3][lr] = a.w;
        float4 w = *(const float4*)(W + (size_t)(colBase + lr)*K + k0 + lc);
        Ws[lc+0][lr] = w.x; Ws[lc+1][lr] = w.y; Ws[lc+2][lr] = w.z; Ws[lc+3][lr] = w.w;
        __syncthreads();
#pragma unroll
        for (int k = 0; k < 16; k++) {
            float4 ra = *(const float4*)&As[k][ty*4];
            float4 rw = *(const float4*)&Ws[k][tx*4];
            acc[0][0] += ra.x*rw.x; acc[0][1] += ra.x*rw.y; acc[0][2] += ra.x*rw.z; acc[0][3] += ra.x*rw.w;
            acc[1][0] += ra.y*rw.x; acc[1][1] += ra.y*rw.y; acc[1][2] += ra.y*rw.z; acc[1][3] += ra.y*rw.w;
            acc[2][0] += ra.z*rw.x; acc[2][1] += ra.z*rw.y; acc[2][2] += ra.z*rw.z; acc[2][3] += ra.z*rw.w;
            acc[3][0] += ra.w*rw.x; acc[3][1] += ra.w*rw.y; acc[3][2] += ra.w*rw.z; acc[3][3] += ra.w*rw.w;
        }
        __syncthreads();
    }
#pragma unroll
    for (int i = 0; i < 4; i++) {
        int r = rowBase + ty*4 + i;
#pragma unroll
        for (int j = 0; j < 4; j++) {
            int c = colBase + tx*4 + j;
            float v = acc[i][j] + bias[c];
            if (doRelu) v = fmaxf(v, 0.f);
            C[(size_t)r*N + c] = v;
        }
    }
}

// ---------------- attention --------------------------------------------------
// Reference semantics: scores = (q.k)*scale for k<=q, EXACTLY 0 for k>q, and
// softmax runs over ALL T entries (masked entries contribute exp(0-m)).
// dh=64. 4 threads per query (each owns 16 dims). Online softmax over j,
// K/V staged in smem in 128-row tiles (64KB dyn smem -> 3 blocks/SM).
// grid (B*H, T/64), block 256.
#define TJ 128
__global__ void attn_kernel(const float* __restrict__ qkv, float* __restrict__ out){
    extern __shared__ float smem[];
    float* Ks = smem;            // [TJ][64]
    float* Vs = smem + TJ*DH;    // [TJ][64]
    int tid = threadIdx.x;
    int b = blockIdx.x >> 3;
    int h = blockIdx.x & 7;
    const float* base = qkv + (size_t)b*Tt*QKVDIM + h*HCH;

    int qLocal  = tid >> 2;          // 0..63
    int quarter = tid & 3;           // 0..3 (16 dims each)
    int qi = blockIdx.y * 64 + qLocal;

    float4 q[4];
    {
        const float4* qp = (const float4*)(base + (size_t)qi*QKVDIM + quarter*16);
        q[0] = qp[0]; q[1] = qp[1]; q[2] = qp[2]; q[3] = qp[3];
    }
    const float scale = 0.125f;      // 1/sqrt(64)

    float m = -1e30f, l = 0.f;
    float4 o0 = make_float4(0,0,0,0), o1 = o0, o2 = o0, o3 = o0;

    for (int j0 = 0; j0 < Tt; j0 += TJ) {
        // stage K,V tile
        for (int i = tid; i < TJ*16; i += 256) {
            int r = i >> 4, f = (i & 15) << 2;
            const float* rowp = base + (size_t)(j0 + r)*QKVDIM;
            *(float4*)(Ks + r*DH + f) = *(const float4*)(rowp + DH  + f);
            *(float4*)(Vs + r*DH + f) = *(const float4*)(rowp + 2*DH + f);
        }
        __syncthreads();

        for (int j = 0; j < TJ; j++) {
            int jj = j0 + j;
            const float4* k4 = (const float4*)(Ks + j*DH + quarter*16);
            float4 k0 = k4[0], k1 = k4[1], k2 = k4[2], k3 = k4[3];
            float s = q[0].x*k0.x + q[0].y*k0.y + q[0].z*k0.z + q[0].w*k0.w
                    + q[1].x*k1.x + q[1].y*k1.y + q[1].z*k1.z + q[1].w*k1.w
                    + q[2].x*k2.x + q[2].y*k2.y + q[2].z*k2.z + q[2].w*k2.w
                    + q[3].x*k3.x + q[3].y*k3.y + q[3].z*k3.z + q[3].w*k3.w;
            // reduce across the 4-thread quarter group
            s += __shfl_xor_sync(0xffffffffu, s, 1);
            s += __shfl_xor_sync(0xffffffffu, s, 2);
            s = (jj <= qi) ? s * scale : 0.0f;

            float m_new = fmaxf(m, s);
            float corr  = __expf(m - m_new);
            float p     = __expf(s - m_new);
            m = m_new;
            l = l*corr + p;
            const float4* v4 = (const float4*)(Vs + j*DH + quarter*16);
            float4 v0 = v4[0], v1 = v4[1], v2 = v4[2], v3 = v4[3];
            o0.x = o0.x*corr + p*v0.x; o0.y = o0.y*corr + p*v0.y; o0.z = o0.z*corr + p*v0.z; o0.w = o0.w*corr + p*v0.w;
            o1.x = o1.x*corr + p*v1.x; o1.y = o1.y*corr + p*v1.y; o1.z = o1.z*corr + p*v1.z; o1.w = o1.w*corr + p*v1.w;
            o2.x = o2.x*corr + p*v2.x; o2.y = o2.y*corr + p*v2.y; o2.z = o2.z*corr + p*v2.z; o2.w = o2.w*corr + p*v2.w;
            o3.x = o3.x*corr + p*v3.x; o3.y = o3.y*corr + p*v3.y; o3.z = o3.z*corr + p*v3.z; o3.w = o3.w*corr + p*v3.w;
        }
        __syncthreads();
    }

    float inv = 1.f / l;
    float* op = out + ((size_t)b*Tt + qi)*Ee + h*DH + quarter*16;
    *(float4*)(op +  0) = make_float4(o0.x*inv, o0.y*inv, o0.z*inv, o0.w*inv);
    *(float4*)(op +  4) = make_float4(o1.x*inv, o1.y*inv, o1.z*inv, o1.w*inv);
    *(float4*)(op +  8) = make_float4(o2.x*inv, o2.y*inv, o2.z*inv, o2.w*inv);
    *(float4*)(op + 12) = make_float4(o3.x*inv, o3.y*inv, o3.z*inv, o3.w*inv);
}

// ---------------- fused residual-add + LayerNorm (warp per row, E=512) -------
__global__ void add_ln_kernel(const float* __restrict__ a, const float* __restrict__ b,
                              const float* __restrict__ gam, const float* __restrict__ bet,
                              float* __restrict__ out){
    int warp = threadIdx.x >> 5, lane = threadIdx.x & 31;
    int row = blockIdx.x * 8 + warp;
    size_t rb = (size_t)row*Ee;
    float xs[16];
    float sum = 0.f, sq = 0.f;
#pragma unroll
    for (int c = 0; c < 4; c++) {
        size_t off = rb + c*128 + lane*4;
        float4 va = *(const float4*)(a + off);
        float4 vb = *(const float4*)(b + off);
        float x0 = va.x+vb.x, x1 = va.y+vb.y, x2 = va.z+vb.z, x3 = va.w+vb.w;
        xs[c*4+0]=x0; xs[c*4+1]=x1; xs[c*4+2]=x2; xs[c*4+3]=x3;
        sum += x0+x1+x2+x3;
        sq  += x0*x0+x1*x1+x2*x2+x3*x3;
    }
    sum = warp_sum(sum);
    sq  = warp_sum(sq);
    float mean = sum * (1.f/(float)Ee);
    float var  = sq  * (1.f/(float)Ee) - mean*mean;
    float r = rsqrtf(var + 1e-5f);
#pragma unroll
    for (int c = 0; c < 4; c++) {
        int col = c*128 + lane*4;
        float4 g  = *(const float4*)(gam + col);
        float4 be = *(const float4*)(bet + col);
        *(float4*)(out + rb + col) = make_float4(
            (xs[c*4+0]-mean)*r*g.x + be.x,
            (xs[c*4+1]-mean)*r*g.y + be.y,
            (xs[c*4+2]-mean)*r*g.z + be.z,
            (xs[c*4+3]-mean)*r*g.w + be.w);
    }
}

// ---------------- loss: per-row smoothed CE, deterministic 2-stage reduce ----
__global__ void loss_rows_kernel(const float* __restrict__ logits,
                                 const void* __restrict__ tgt,
                                 float* __restrict__ partials){
    __shared__ float rvals[8];
    int warp = threadIdx.x >> 5, lane = threadIdx.x & 31;
    int row = blockIdx.x * 8 + warp;
    const float* lp = logits + (size_t)row*Vv;
    float4 v = *(const float4*)(lp + lane*4);
    float mx = warp_max(fmaxf(fmaxf(v.x, v.y), fmaxf(v.z, v.w)));
    float sm = warp_sum(v.x + v.y + v.z + v.w);
    float se = warp_sum(__expf(v.x-mx) + __expf(v.y-mx) + __expf(v.z-mx) + __expf(v.w-mx));
    if (lane == 0) {
        float logZ = mx + logf(se);
        int t = get_tok(tgt, row);
        float nll    = logZ - lp[t];
        float smooth = logZ - sm * (1.f/(float)Vv);
        rvals[warp] = 0.9f*nll + 0.1f*smooth;
    }
    __syncthreads();
    if (threadIdx.x == 0) {
        float s = 0.f;
        for (int i = 0; i < 8; i++) s += rvals[i];
        partials[blockIdx.x] = s;
    }
}

__global__ void loss_final_kernel(const float* __restrict__ partials, float* __restrict__ out){
    __shared__ float s[512];
    int tid = threadIdx.x;
    s[tid] = partials[tid];
    __syncthreads();
    for (int o = 256; o; o >>= 1) {
        if (tid < o) s[tid] += s[tid + o];
        __syncthreads();
    }
    if (tid == 0) out[0] = s[0] * (1.f/(float)NTOK);
}

// ---------------- launch ------------------------------------------------------
extern "C" void kernel_launch(void* const* d_in, const int* in_sizes, int n_in,
                              void* d_out, int out_size){
    // Ordering dispatch. With E=512, aff1_b also has 4096 elements, so slot 0
    // is ambiguous. Slot 1 disambiguates: insertion order -> targets (4096);
    // alphabetical -> aff1_w (2,097,152).
    const void *inputs, *targets;
    const float *emb, *qkv_w, *qkv_b, *aff1_w, *aff1_b, *aff2_w, *aff2_b;
    const float *ffn1_w, *ffn1_b, *ffn2_w, *ffn2_b;
    const float *ln1_s, *ln1_b, *ln2_s, *ln2_b, *head_w, *head_b;

    if (in_sizes[1] > 100000) {
        // alphabetical: aff1_b, aff1_w, aff2_b, aff2_w, emb, ffn1_b, ffn1_w,
        // ffn2_b, ffn2_w, head_b, head_w, inputs, ln1_b, ln1_s, ln2_b, ln2_s,
        // qkv_b, qkv_w, targets
        aff1_b = (const float*)d_in[0];
        aff1_w = (const float*)d_in[1];
        aff2_b = (const float*)d_in[2];
        aff2_w = (const float*)d_in[3];
        emb    = (const float*)d_in[4];
        ffn1_b = (const float*)d_in[5];
        ffn1_w = (const float*)d_in[6];
        ffn2_b = (const float*)d_in[7];
        ffn2_w = (const float*)d_in[8];
        head_b = (const float*)d_in[9];
        head_w = (const float*)d_in[10];
        inputs = d_in[11];
        ln1_b  = (const float*)d_in[12];
        ln1_s  = (const float*)d_in[13];
        ln2_b  = (const float*)d_in[14];
        ln2_s  = (const float*)d_in[15];
        qkv_b  = (const float*)d_in[16];
        qkv_w  = (const float*)d_in[17];
        targets= d_in[18];
    } else {
        // insertion / signature order
        inputs  = d_in[0];
        targets = d_in[1];
        emb     = (const float*)d_in[2];
        qkv_w   = (const float*)d_in[3];
        qkv_b   = (const float*)d_in[4];
        aff1_w  = (const float*)d_in[5];
        aff1_b  = (const float*)d_in[6];
        aff2_w  = (const float*)d_in[7];
        aff2_b  = (const float*)d_in[8];
        ffn1_w  = (const float*)d_in[9];
        ffn1_b  = (const float*)d_in[10];
        ffn2_w  = (const float*)d_in[11];
        ffn2_b  = (const float*)d_in[12];
        ln1_s   = (const float*)d_in[13];
        ln1_b   = (const float*)d_in[14];
        ln2_s   = (const float*)d_in[15];
        ln2_b   = (const float*)d_in[16];
        head_w  = (const float*)d_in[17];
        head_b  = (const float*)d_in[18];
    }
    float* out = (float*)d_out;

    float *x, *qkv, *att, *tmp, *aff, *out1, *logits_scratch, *partials;
    cudaGetSymbolAddress((void**)&x,    g_x);
    cudaGetSymbolAddress((void**)&qkv,  g_qkv);
    cudaGetSymbolAddress((void**)&att,  g_att);
    cudaGetSymbolAddress((void**)&tmp,  g_tmp);
    cudaGetSymbolAddress((void**)&aff,  g_aff);
    cudaGetSymbolAddress((void**)&out1, g_out1);
    cudaGetSymbolAddress((void**)&logits_scratch, g_logits);
    cudaGetSymbolAddress((void**)&partials, g_partials);

    const int BTV = NTOK * Vv;                      // 524288
    float* logits_dst = (out_size >= BTV) ? out : logits_scratch;
    float* loss_dst   = (out_size > BTV) ? (out + BTV)
                       : ((out_size > 0 && out_size < BTV) ? out : nullptr);

    const int ATTN_SMEM = 2 * TJ * DH * (int)sizeof(float);  // 65536
    cudaFuncSetAttribute(attn_kernel, cudaFuncAttributeMaxDynamicSharedMemorySize, ATTN_SMEM);

    detect_kernel<<<1, 1>>>((const int*)inputs);
    embed_kernel<<<NTOK, 128>>>(inputs, emb, x);

    dim3 gQKV(QKVDIM/64, NTOK/64);   // (24,64)
    dim3 gE  (Ee/64,     NTOK/64);   // (8,64)
    dim3 gHead(Vv/64,    NTOK/64);   // (2,64)
    dim3 gAtt(Bsz*Hh, Tt/64);        // (32,16)

    for (int l = 0; l < Ll; l++) {
        gemm_bias_kernel<<<gQKV, 256>>>(x, qkv_w + (size_t)l*QKVDIM*Ee, qkv_b + (size_t)l*QKVDIM, qkv, QKVDIM, Ee, 0);
        attn_kernel<<<gAtt, 256, ATTN_SMEM>>>(qkv, att);
        gemm_bias_kernel<<<gE, 256>>>(att, aff1_w + (size_t)l*Ee*Ee, aff1_b + (size_t)l*Ee, tmp, Ee, Ee, 1);
        gemm_bias_kernel<<<gE, 256>>>(tmp, aff2_w + (size_t)l*Ee*Ee, aff2_b + (size_t)l*Ee, aff, Ee, Ee, 0);
        add_ln_kernel<<<NTOK/8, 256>>>(aff, x, ln1_s + (size_t)l*Ee, ln1_b + (size_t)l*Ee, out1);
        gemm_bias_kernel<<<gE, 256>>>(out1, ffn1_w + (size_t)l*Ee*Ee, ffn1_b + (size_t)l*Ee, tmp, Ee, Ee, 1);
        gemm_bias_kernel<<<gE, 256>>>(tmp, ffn2_w + (size_t)l*Ee*Ee, ffn2_b + (size_t)l*Ee, aff, Ee, Ee, 0);
        add_ln_kernel<<<NTOK/8, 256>>>(out1, aff, ln2_s + (size_t)l*Ee, ln2_b + (size_t)l*Ee, x);
    }

    gemm_bias_kernel<<<gHead, 256>>>(x, head_w, head_b, logits_dst, Vv, Ee, 0);
    loss_rows_kernel<<<NTOK/8, 256>>>(logits_dst, targets, partials);
    if (loss_dst)
        loss_final_kernel<<<1, 512>>>(partials, loss_dst);
}

// round 6
// speedup vs baseline: 1.7444x; 1.7444x over previous
#include <cuda_runtime.h>
#include <cuda_bf16.h>

// Problem constants (V,E,L,H = 128,512,8,8; B,T = 4,1024)
#define Bsz 4
#define Tt  1024
#define Vv  128
#define Ee  512
#define Hh  8
#define Ll  8
#define DH  64
#define NTOK (Bsz*Tt)          // 4096
#define QKVDIM (3*Ee)          // 1536
#define HCH (3*DH)             // 192 per-head chunk in qkv row

// ---------------- scratch (device globals; no allocation allowed) -----------
__device__ float g_x   [NTOK*Ee];
__device__ float g_qkv [NTOK*QKVDIM];
__device__ float g_att [NTOK*Ee];
__device__ float g_tmp [NTOK*Ee];
__device__ float g_aff [NTOK*Ee];
__device__ float g_out1[NTOK*Ee];
__device__ float g_sv  [Bsz*Hh*Tt*DH];   // suffix sums of V per (b,h)
__device__ float g_logits[NTOK*Vv];
__device__ float g_partials[512];
__device__ int   g_is32;

// ---------------- f32x2 packed helpers (FFMA2 on sm_103a) --------------------
__device__ __forceinline__ unsigned long long dl(double d){ return __double_as_longlong(d); }
__device__ __forceinline__ unsigned long long pack2(float x){
    unsigned long long r; asm("mov.b64 %0, {%1, %1};" : "=l"(r) : "f"(x)); return r;
}
__device__ __forceinline__ void fma2(unsigned long long &acc, unsigned long long a, unsigned long long b){
    asm("fma.rn.f32x2 %0, %1, %2, %0;" : "+l"(acc) : "l"(a), "l"(b));
}
__device__ __forceinline__ unsigned long long fma2v(unsigned long long a, unsigned long long b, unsigned long long c){
    unsigned long long d; asm("fma.rn.f32x2 %0, %1, %2, %3;" : "=l"(d) : "l"(a), "l"(b), "l"(c)); return d;
}
__device__ __forceinline__ unsigned long long mul2(unsigned long long a, unsigned long long b){
    unsigned long long d; asm("mul.rn.f32x2 %0, %1, %2;" : "=l"(d) : "l"(a), "l"(b)); return d;
}
__device__ __forceinline__ unsigned long long add2(unsigned long long a, unsigned long long b){
    unsigned long long d; asm("add.rn.f32x2 %0, %1, %2;" : "=l"(d) : "l"(a), "l"(b)); return d;
}
__device__ __forceinline__ float2 unpk2(unsigned long long v){
    float lo, hi; asm("mov.b64 {%0, %1}, %2;" : "=f"(lo), "=f"(hi) : "l"(v)); return make_float2(lo, hi);
}

// ---------------- misc helpers -----------------------------------------------
__device__ __forceinline__ float warp_sum(float v){
#pragma unroll
    for (int o = 16; o; o >>= 1) v += __shfl_xor_sync(0xffffffffu, v, o);
    return v;
}
__device__ __forceinline__ float warp_max(float v){
#pragma unroll
    for (int o = 16; o; o >>= 1) v = fmaxf(v, __shfl_xor_sync(0xffffffffu, v, o));
    return v;
}
__device__ __forceinline__ int get_tok(const void* p, int i){
    return g_is32 ? ((const int*)p)[i] : (int)((const long long*)p)[i];
}

__global__ void detect_kernel(const int* __restrict__ inp){
    int is32 = 0;
    for (int i = 1; i < 128; i += 2) if (inp[i] != 0) { is32 = 1; break; }
    g_is32 = is32;
}

// ---------------- embedding --------------------------------------------------
__global__ void embed_kernel(const void* __restrict__ inp,
                             const float* __restrict__ emb,
                             float* __restrict__ x){
    int t = blockIdx.x;
    int tok = get_tok(inp, t);
    *(float4*)(x + (size_t)t*Ee + threadIdx.x*4) =
        *(const float4*)(emb + (size_t)tok*Ee + threadIdx.x*4);
}

// ---------------- GEMM: C = A[M,K] @ W[N,K]^T + bias (opt relu), FFMA2 -------
// Block tile 128x64, 256 threads, per-thread 8x4 (rows packed in f32x2 pairs).
#define BM 128
#define BN 64
#define BK 16
__global__ void gemm_bias_kernel(const float* __restrict__ A,
                                 const float* __restrict__ W,
                                 const float* __restrict__ bias,
                                 float* __restrict__ C,
                                 int N, int K, int doRelu){
    __shared__ __align__(16) float As[BK][BM];
    __shared__ __align__(16) float Ws[BK][BN];
    int tid = threadIdx.x;
    int rowBase = blockIdx.y * BM;
    int colBase = blockIdx.x * BN;
    int ty = tid >> 4;           // 0..15 -> rows ty*8
    int tx = tid & 15;           // 0..15 -> cols tx*4
    int ar = tid >> 1;           // 0..127
    int ak = (tid & 1) * 8;      // 0 or 8
    int wr = tid >> 2;           // 0..63
    int wk = (tid & 3) * 4;      // 0,4,8,12

    unsigned long long acc[4][4];
#pragma unroll
    for (int i = 0; i < 4; i++)
#pragma unroll
        for (int j = 0; j < 4; j++) acc[i][j] = 0ull;

    for (int k0 = 0; k0 < K; k0 += BK) {
        const float* arow = A + (size_t)(rowBase + ar)*K + k0 + ak;
        float4 a0 = *(const float4*)(arow);
        float4 a1 = *(const float4*)(arow + 4);
        As[ak+0][ar]=a0.x; As[ak+1][ar]=a0.y; As[ak+2][ar]=a0.z; As[ak+3][ar]=a0.w;
        As[ak+4][ar]=a1.x; As[ak+5][ar]=a1.y; As[ak+6][ar]=a1.z; As[ak+7][ar]=a1.w;
        float4 w = *(const float4*)(W + (size_t)(colBase + wr)*K + k0 + wk);
        Ws[wk+0][wr]=w.x; Ws[wk+1][wr]=w.y; Ws[wk+2][wr]=w.z; Ws[wk+3][wr]=w.w;
        __syncthreads();
#pragma unroll
        for (int k = 0; k < BK; k++) {
            const double2* ap = (const double2*)&As[k][ty*8];
            double2 ad0 = ap[0], ad1 = ap[1];
            unsigned long long ap0 = dl(ad0.x), ap1 = dl(ad0.y);
            unsigned long long ap2 = dl(ad1.x), ap3 = dl(ad1.y);
            float4 bw = *(const float4*)&Ws[k][tx*4];
            unsigned long long b0 = pack2(bw.x), b1 = pack2(bw.y);
            unsigned long long b2 = pack2(bw.z), b3 = pack2(bw.w);
            fma2(acc[0][0], ap0, b0); fma2(acc[0][1], ap0, b1); fma2(acc[0][2], ap0, b2); fma2(acc[0][3], ap0, b3);
            fma2(acc[1][0], ap1, b0); fma2(acc[1][1], ap1, b1); fma2(acc[1][2], ap1, b2); fma2(acc[1][3], ap1, b3);
            fma2(acc[2][0], ap2, b0); fma2(acc[2][1], ap2, b1); fma2(acc[2][2], ap2, b2); fma2(acc[2][3], ap2, b3);
            fma2(acc[3][0], ap3, b0); fma2(acc[3][1], ap3, b1); fma2(acc[3][2], ap3, b2); fma2(acc[3][3], ap3, b3);
        }
        __syncthreads();
    }

    int c = colBase + tx*4;
    float4 b4 = *(const float4*)(bias + c);
#pragma unroll
    for (int i2 = 0; i2 < 4; i2++) {
        float2 u0 = unpk2(acc[i2][0]);
        float2 u1 = unpk2(acc[i2][1]);
        float2 u2 = unpk2(acc[i2][2]);
        float2 u3 = unpk2(acc[i2][3]);
        float4 lo = make_float4(u0.x+b4.x, u1.x+b4.y, u2.x+b4.z, u3.x+b4.w);
        float4 hi = make_float4(u0.y+b4.x, u1.y+b4.y, u2.y+b4.z, u3.y+b4.w);
        if (doRelu) {
            lo.x=fmaxf(lo.x,0.f); lo.y=fmaxf(lo.y,0.f); lo.z=fmaxf(lo.z,0.f); lo.w=fmaxf(lo.w,0.f);
            hi.x=fmaxf(hi.x,0.f); hi.y=fmaxf(hi.y,0.f); hi.z=fmaxf(hi.z,0.f); hi.w=fmaxf(hi.w,0.f);
        }
        int r0 = rowBase + ty*8 + i2*2;
        *(float4*)(C + (size_t)r0*N + c)     = lo;
        *(float4*)(C + (size_t)(r0+1)*N + c) = hi;
    }
}

// ---------------- suffix-V sums per (b,h): SV[j] = sum_{t>=j} V[t] -----------
// grid 32, block 512 (8 segments x 64 dims)
__global__ void svsum_kernel(const float* __restrict__ qkv, float* __restrict__ sv){
    __shared__ float segsum[8][64];
    int bh = blockIdx.x, b = bh >> 3, h = bh & 7;
    const float* vbase = qkv + (size_t)b*Tt*QKVDIM + h*HCH + 2*DH;
    int seg = threadIdx.x >> 6, d = threadIdx.x & 63;
    int j0 = seg * 128;
    float acc = 0.f;
    for (int j = j0; j < j0 + 128; j++) acc += vbase[(size_t)j*QKVDIM + d];
    segsum[seg][d] = acc;
    __syncthreads();
    float tl = 0.f;
    for (int s2 = seg + 1; s2 < 8; s2++) tl += segsum[s2][d];
    float* svb = sv + (size_t)bh*Tt*DH;
    acc = tl;
    for (int j = j0 + 127; j >= j0; j--) {
        acc += vbase[(size_t)j*QKVDIM + d];
        svb[(size_t)j*DH + d] = acc;
    }
}

// ---------------- attention --------------------------------------------------
// tril-multiply semantics: s_j = (q.k_j)*scale for j<=qi, EXACTLY 0 for j>qi,
// softmax over ALL T. Online pass over j<=qi only; masked tail added
// analytically: l += (T-1-qi)*exp(-m), o += exp(-m)*SV[qi+1].
// grid (B*H, T/64), block 256 (4 threads/query), dyn smem 64KB.
#define TJ 128
__global__ void attn_kernel(const float* __restrict__ qkv,
                            const float* __restrict__ sv,
                            float* __restrict__ out){
    extern __shared__ float smem[];
    float* Ks = smem;            // [TJ][64]
    float* Vs = smem + TJ*DH;    // [TJ][64]
    int tid = threadIdx.x;
    int b = blockIdx.x >> 3;
    int h = blockIdx.x & 7;
    const float* base = qkv + (size_t)b*Tt*QKVDIM + h*HCH;

    int qLocal  = tid >> 2;
    int quarter = tid & 3;
    int qi = blockIdx.y * 64 + qLocal;
    int lane = tid & 31;
    unsigned grpmask = 0xFu << (lane & 28);
    int qiWarpMax = blockIdx.y * 64 + ((tid >> 5) << 3) + 7;
    const float scale = 0.125f;      // 1/sqrt(64)

    unsigned long long qp[8];
    {
        const double2* qd = (const double2*)(base + (size_t)qi*QKVDIM + quarter*16);
        double2 d0 = qd[0], d1 = qd[1], d2 = qd[2], d3 = qd[3];
        qp[0]=dl(d0.x); qp[1]=dl(d0.y); qp[2]=dl(d1.x); qp[3]=dl(d1.y);
        qp[4]=dl(d2.x); qp[5]=dl(d2.y); qp[6]=dl(d3.x); qp[7]=dl(d3.y);
    }

    float m = -1e30f, l = 0.f;
    unsigned long long o[8];
#pragma unroll
    for (int i = 0; i < 8; i++) o[i] = 0ull;

    int jmaxBlock = blockIdx.y * 64 + 63;
    for (int j0 = 0; j0 <= jmaxBlock; j0 += TJ) {
        for (int i = tid; i < TJ*16; i += 256) {
            int r = i >> 4, f = (i & 15) << 2;
            const float* rowp = base + (size_t)(j0 + r)*QKVDIM;
            *(float4*)(Ks + r*DH + f) = *(const float4*)(rowp + DH   + f);
            *(float4*)(Vs + r*DH + f) = *(const float4*)(rowp + 2*DH + f);
        }
        __syncthreads();

        int jlim = min(TJ, qiWarpMax - j0 + 1);   // warp-uniform
        for (int j = 0; j < jlim; j++) {
            int jj = j0 + j;
            if (jj <= qi) {                        // uniform across 4-lane group
                const double2* kd = (const double2*)(Ks + j*DH + quarter*16);
                double2 k0 = kd[0], k1 = kd[1], k2 = kd[2], k3 = kd[3];
                unsigned long long d0 = 0ull, d1 = 0ull;
                d0 = fma2v(qp[0], dl(k0.x), d0); d1 = fma2v(qp[1], dl(k0.y), d1);
                d0 = fma2v(qp[2], dl(k1.x), d0); d1 = fma2v(qp[3], dl(k1.y), d1);
                d0 = fma2v(qp[4], dl(k2.x), d0); d1 = fma2v(qp[5], dl(k2.y), d1);
                d0 = fma2v(qp[6], dl(k3.x), d0); d1 = fma2v(qp[7], dl(k3.y), d1);
                float2 ds = unpk2(add2(d0, d1));
                float s = ds.x + ds.y;
                s += __shfl_xor_sync(grpmask, s, 1);
                s += __shfl_xor_sync(grpmask, s, 2);
                s *= scale;
                float m_new = fmaxf(m, s);
                float corr  = __expf(m - m_new);
                float p     = __expf(s - m_new);
                m = m_new;
                l = l*corr + p;
                unsigned long long pp = pack2(p), cp = pack2(corr);
                const double2* vd = (const double2*)(Vs + j*DH + quarter*16);
                double2 v0 = vd[0], v1 = vd[1], v2 = vd[2], v3 = vd[3];
                o[0] = fma2v(o[0], cp, mul2(pp, dl(v0.x)));
                o[1] = fma2v(o[1], cp, mul2(pp, dl(v0.y)));
                o[2] = fma2v(o[2], cp, mul2(pp, dl(v1.x)));
                o[3] = fma2v(o[3], cp, mul2(pp, dl(v1.y)));
                o[4] = fma2v(o[4], cp, mul2(pp, dl(v2.x)));
                o[5] = fma2v(o[5], cp, mul2(pp, dl(v2.y)));
                o[6] = fma2v(o[6], cp, mul2(pp, dl(v3.x)));
                o[7] = fma2v(o[7], cp, mul2(pp, dl(v3.y)));
            }
        }
        __syncthreads();
    }

    // analytic masked tail (scores exactly 0 for j>qi)
    if (qi < Tt - 1) {
        float m_f  = fmaxf(m, 0.f);
        float corr = __expf(m - m_f);
        float tail = __expf(0.f - m_f);
        l = l*corr + (float)(Tt - 1 - qi)*tail;
        unsigned long long cp = pack2(corr), tp = pack2(tail);
        const double2* svd = (const double2*)(sv + ((size_t)blockIdx.x*Tt + (qi+1))*DH + quarter*16);
        double2 s0 = svd[0], s1 = svd[1], s2 = svd[2], s3 = svd[3];
        o[0] = fma2v(o[0], cp, mul2(tp, dl(s0.x)));
        o[1] = fma2v(o[1], cp, mul2(tp, dl(s0.y)));
        o[2] = fma2v(o[2], cp, mul2(tp, dl(s1.x)));
        o[3] = fma2v(o[3], cp, mul2(tp, dl(s1.y)));
        o[4] = fma2v(o[4], cp, mul2(tp, dl(s2.x)));
        o[5] = fma2v(o[5], cp, mul2(tp, dl(s2.y)));
        o[6] = fma2v(o[6], cp, mul2(tp, dl(s3.x)));
        o[7] = fma2v(o[7], cp, mul2(tp, dl(s3.y)));
    }

    float inv = 1.f / l;
    unsigned long long ip = pack2(inv);
    float2 u0 = unpk2(mul2(o[0], ip)), u1 = unpk2(mul2(o[1], ip));
    float2 u2 = unpk2(mul2(o[2], ip)), u3 = unpk2(mul2(o[3], ip));
    float2 u4 = unpk2(mul2(o[4], ip)), u5 = unpk2(mul2(o[5], ip));
    float2 u6 = unpk2(mul2(o[6], ip)), u7 = unpk2(mul2(o[7], ip));
    float* op = out + ((size_t)b*Tt + qi)*Ee + h*DH + quarter*16;
    *(float4*)(op +  0) = make_float4(u0.x, u0.y, u1.x, u1.y);
    *(float4*)(op +  4) = make_float4(u2.x, u2.y, u3.x, u3.y);
    *(float4*)(op +  8) = make_float4(u4.x, u4.y, u5.x, u5.y);
    *(float4*)(op + 12) = make_float4(u6.x, u6.y, u7.x, u7.y);
}

// ---------------- fused residual-add + LayerNorm (warp per row, E=512) -------
__global__ void add_ln_kernel(const float* __restrict__ a, const float* __restrict__ b,
                              const float* __restrict__ gam, const float* __restrict__ bet,
                              float* __restrict__ out){
    int warp = threadIdx.x >> 5, lane = threadIdx.x & 31;
    int row = blockIdx.x * 8 + warp;
    size_t rb = (size_t)row*Ee;
    float xs[16];
    float sum = 0.f, sq = 0.f;
#pragma unroll
    for (int c = 0; c < 4; c++) {
        size_t off = rb + c*128 + lane*4;
        float4 va = *(const float4*)(a + off);
        float4 vb = *(const float4*)(b + off);
        float x0 = va.x+vb.x, x1 = va.y+vb.y, x2 = va.z+vb.z, x3 = va.w+vb.w;
        xs[c*4+0]=x0; xs[c*4+1]=x1; xs[c*4+2]=x2; xs[c*4+3]=x3;
        sum += x0+x1+x2+x3;
        sq  += x0*x0+x1*x1+x2*x2+x3*x3;
    }
    sum = warp_sum(sum);
    sq  = warp_sum(sq);
    float mean = sum * (1.f/(float)Ee);
    float var  = sq  * (1.f/(float)Ee) - mean*mean;
    float r = rsqrtf(var + 1e-5f);
#pragma unroll
    for (int c = 0; c < 4; c++) {
        int col = c*128 + lane*4;
        float4 g  = *(const float4*)(gam + col);
        float4 be = *(const float4*)(bet + col);
        *(float4*)(out + rb + col) = make_float4(
            (xs[c*4+0]-mean)*r*g.x + be.x,
            (xs[c*4+1]-mean)*r*g.y + be.y,
            (xs[c*4+2]-mean)*r*g.z + be.z,
            (xs[c*4+3]-mean)*r*g.w + be.w);
    }
}

// ---------------- loss: per-row smoothed CE, deterministic 2-stage reduce ----
__global__ void loss_rows_kernel(const float* __restrict__ logits,
                                 const void* __restrict__ tgt,
                                 float* __restrict__ partials){
    __shared__ float rvals[8];
    int warp = threadIdx.x >> 5, lane = threadIdx.x & 31;
    int row = blockIdx.x * 8 + warp;
    const float* lp = logits + (size_t)row*Vv;
    float4 v = *(const float4*)(lp + lane*4);
    float mx = warp_max(fmaxf(fmaxf(v.x, v.y), fmaxf(v.z, v.w)));
    float sm = warp_sum(v.x + v.y + v.z + v.w);
    float se = warp_sum(__expf(v.x-mx) + __expf(v.y-mx) + __expf(v.z-mx) + __expf(v.w-mx));
    if (lane == 0) {
        float logZ = mx + logf(se);
        int t = get_tok(tgt, row);
        float nll    = logZ - lp[t];
        float smooth = logZ - sm * (1.f/(float)Vv);
        rvals[warp] = 0.9f*nll + 0.1f*smooth;
    }
    __syncthreads();
    if (threadIdx.x == 0) {
        float s = 0.f;
        for (int i = 0; i < 8; i++) s += rvals[i];
        partials[blockIdx.x] = s;
    }
}

__global__ void loss_final_kernel(const float* __restrict__ partials, float* __restrict__ out){
    __shared__ float s[512];
    int tid = threadIdx.x;
    s[tid] = partials[tid];
    __syncthreads();
    for (int o = 256; o; o >>= 1) {
        if (tid < o) s[tid] += s[tid + o];
        __syncthreads();
    }
    if (tid == 0) out[0] = s[0] * (1.f/(float)NTOK);
}

// ---------------- launch ------------------------------------------------------
extern "C" void kernel_launch(void* const* d_in, const int* in_sizes, int n_in,
                              void* d_out, int out_size){
    const void *inputs, *targets;
    const float *emb, *qkv_w, *qkv_b, *aff1_w, *aff1_b, *aff2_w, *aff2_b;
    const float *ffn1_w, *ffn1_b, *ffn2_w, *ffn2_b;
    const float *ln1_s, *ln1_b, *ln2_s, *ln2_b, *head_w, *head_b;

    if (in_sizes[1] > 100000) {
        // alphabetical ordering
        aff1_b = (const float*)d_in[0];
        aff1_w = (const float*)d_in[1];
        aff2_b = (const float*)d_in[2];
        aff2_w = (const float*)d_in[3];
        emb    = (const float*)d_in[4];
        ffn1_b = (const float*)d_in[5];
        ffn1_w = (const float*)d_in[6];
        ffn2_b = (const float*)d_in[7];
        ffn2_w = (const float*)d_in[8];
        head_b = (const float*)d_in[9];
        head_w = (const float*)d_in[10];
        inputs = d_in[11];
        ln1_b  = (const float*)d_in[12];
        ln1_s  = (const float*)d_in[13];
        ln2_b  = (const float*)d_in[14];
        ln2_s  = (const float*)d_in[15];
        qkv_b  = (const float*)d_in[16];
        qkv_w  = (const float*)d_in[17];
        targets= d_in[18];
    } else {
        // signature / insertion ordering
        inputs  = d_in[0];
        targets = d_in[1];
        emb     = (const float*)d_in[2];
        qkv_w   = (const float*)d_in[3];
        qkv_b   = (const float*)d_in[4];
        aff1_w  = (const float*)d_in[5];
        aff1_b  = (const float*)d_in[6];
        aff2_w  = (const float*)d_in[7];
        aff2_b  = (const float*)d_in[8];
        ffn1_w  = (const float*)d_in[9];
        ffn1_b  = (const float*)d_in[10];
        ffn2_w  = (const float*)d_in[11];
        ffn2_b  = (const float*)d_in[12];
        ln1_s   = (const float*)d_in[13];
        ln1_b   = (const float*)d_in[14];
        ln2_s   = (const float*)d_in[15];
        ln2_b   = (const float*)d_in[16];
        head_w  = (const float*)d_in[17];
        head_b  = (const float*)d_in[18];
    }
    float* out = (float*)d_out;

    float *x, *qkv, *att, *tmp, *aff, *out1, *sv, *logits_scratch, *partials;
    cudaGetSymbolAddress((void**)&x,    g_x);
    cudaGetSymbolAddress((void**)&qkv,  g_qkv);
    cudaGetSymbolAddress((void**)&att,  g_att);
    cudaGetSymbolAddress((void**)&tmp,  g_tmp);
    cudaGetSymbolAddress((void**)&aff,  g_aff);
    cudaGetSymbolAddress((void**)&out1, g_out1);
    cudaGetSymbolAddress((void**)&sv,   g_sv);
    cudaGetSymbolAddress((void**)&logits_scratch, g_logits);
    cudaGetSymbolAddress((void**)&partials, g_partials);

    const int BTV = NTOK * Vv;                      // 524288
    float* logits_dst = (out_size >= BTV) ? out : logits_scratch;
    float* loss_dst   = (out_size > BTV) ? (out + BTV)
                       : ((out_size > 0 && out_size < BTV) ? out : nullptr);

    const int ATTN_SMEM = 2 * TJ * DH * (int)sizeof(float);  // 65536
    cudaFuncSetAttribute(attn_kernel, cudaFuncAttributeMaxDynamicSharedMemorySize, ATTN_SMEM);

    detect_kernel<<<1, 1>>>((const int*)inputs);
    embed_kernel<<<NTOK, 128>>>(inputs, emb, x);

    dim3 gQKV(QKVDIM/BN, NTOK/BM);   // (24,32)
    dim3 gE  (Ee/BN,     NTOK/BM);   // (8,32)
    dim3 gHead(Vv/BN,    NTOK/BM);   // (2,32)
    dim3 gAtt(Bsz*Hh, Tt/64);        // (32,16)

    for (int l = 0; l < Ll; l++) {
        gemm_bias_kernel<<<gQKV, 256>>>(x, qkv_w + (size_t)l*QKVDIM*Ee, qkv_b + (size_t)l*QKVDIM, qkv, QKVDIM, Ee, 0);
        svsum_kernel<<<Bsz*Hh, 512>>>(qkv, sv);
        attn_kernel<<<gAtt, 256, ATTN_SMEM>>>(qkv, sv, att);
        gemm_bias_kernel<<<gE, 256>>>(att, aff1_w + (size_t)l*Ee*Ee, aff1_b + (size_t)l*Ee, tmp, Ee, Ee, 1);
        gemm_bias_kernel<<<gE, 256>>>(tmp, aff2_w + (size_t)l*Ee*Ee, aff2_b + (size_t)l*Ee, aff, Ee, Ee, 0);
        add_ln_kernel<<<NTOK/8, 256>>>(aff, x, ln1_s + (size_t)l*Ee, ln1_b + (size_t)l*Ee, out1);
        gemm_bias_kernel<<<gE, 256>>>(out1, ffn1_w + (size_t)l*Ee*Ee, ffn1_b + (size_t)l*Ee, tmp, Ee, Ee, 1);
        gemm_bias_kernel<<<gE, 256>>>(tmp, ffn2_w + (size_t)l*Ee*Ee, ffn2_b + (size_t)l*Ee, aff, Ee, Ee, 0);
        add_ln_kernel<<<NTOK/8, 256>>>(out1, aff, ln2_s + (size_t)l*Ee, ln2_b + (size_t)l*Ee, x);
    }

    gemm_bias_kernel<<<gHead, 256>>>(x, head_w, head_b, logits_dst, Vv, Ee, 0);
    loss_rows_kernel<<<NTOK/8, 256>>>(logits_dst, targets, partials);
    if (loss_dst)
        loss_final_kernel<<<1, 512>>>(partials, loss_dst);
}

// round 7
// speedup vs baseline: 1.8193x; 1.0430x over previous
#include <cuda_runtime.h>
#include <cuda_bf16.h>

// Problem constants (V,E,L,H = 128,512,8,8; B,T = 4,1024)
#define Bsz 4
#define Tt  1024
#define Vv  128
#define Ee  512
#define Hh  8
#define Ll  8
#define DH  64
#define NTOK (Bsz*Tt)          // 4096
#define QKVDIM (3*Ee)          // 1536
#define HCH (3*DH)             // 192 per-head chunk in qkv row

// ---------------- scratch (device globals; no allocation allowed) -----------
__device__ float g_x   [NTOK*Ee];
__device__ float g_qkv [NTOK*QKVDIM];
__device__ float g_att [NTOK*Ee];
__device__ float g_tmp [NTOK*Ee];
__device__ float g_aff [NTOK*Ee];
__device__ float g_out1[NTOK*Ee];
__device__ float g_sv  [Bsz*Hh*Tt*DH];   // suffix sums of V per (b,h)
__device__ float g_logits[NTOK*Vv];
__device__ float g_partials[512];
__device__ int   g_is32;

// ---------------- f32x2 packed helpers (FFMA2 on sm_103a) --------------------
__device__ __forceinline__ unsigned long long dl(double d){ return __double_as_longlong(d); }
__device__ __forceinline__ unsigned long long pack2(float x){
    unsigned long long r; asm("mov.b64 %0, {%1, %1};" : "=l"(r) : "f"(x)); return r;
}
__device__ __forceinline__ void fma2(unsigned long long &acc, unsigned long long a, unsigned long long b){
    asm("fma.rn.f32x2 %0, %1, %2, %0;" : "+l"(acc) : "l"(a), "l"(b));
}
__device__ __forceinline__ unsigned long long fma2v(unsigned long long a, unsigned long long b, unsigned long long c){
    unsigned long long d; asm("fma.rn.f32x2 %0, %1, %2, %3;" : "=l"(d) : "l"(a), "l"(b), "l"(c)); return d;
}
__device__ __forceinline__ unsigned long long mul2(unsigned long long a, unsigned long long b){
    unsigned long long d; asm("mul.rn.f32x2 %0, %1, %2;" : "=l"(d) : "l"(a), "l"(b)); return d;
}
__device__ __forceinline__ unsigned long long add2(unsigned long long a, unsigned long long b){
    unsigned long long d; asm("add.rn.f32x2 %0, %1, %2;" : "=l"(d) : "l"(a), "l"(b)); return d;
}
__device__ __forceinline__ float2 unpk2(unsigned long long v){
    float lo, hi; asm("mov.b64 {%0, %1}, %2;" : "=f"(lo), "=f"(hi) : "l"(v)); return make_float2(lo, hi);
}

// ---------------- misc helpers -----------------------------------------------
__device__ __forceinline__ float warp_sum(float v){
#pragma unroll
    for (int o = 16; o; o >>= 1) v += __shfl_xor_sync(0xffffffffu, v, o);
    return v;
}
__device__ __forceinline__ float warp_max(float v){
#pragma unroll
    for (int o = 16; o; o >>= 1) v = fmaxf(v, __shfl_xor_sync(0xffffffffu, v, o));
    return v;
}
__device__ __forceinline__ int get_tok(const void* p, int i){
    return g_is32 ? ((const int*)p)[i] : (int)((const long long*)p)[i];
}

__global__ void detect_kernel(const int* __restrict__ inp){
    int is32 = 0;
    for (int i = 1; i < 128; i += 2) if (inp[i] != 0) { is32 = 1; break; }
    g_is32 = is32;
}

// ---------------- embedding --------------------------------------------------
__global__ void embed_kernel(const void* __restrict__ inp,
                             const float* __restrict__ emb,
                             float* __restrict__ x){
    int t = blockIdx.x;
    int tok = get_tok(inp, t);
    *(float4*)(x + (size_t)t*Ee + threadIdx.x*4) =
        *(const float4*)(emb + (size_t)tok*Ee + threadIdx.x*4);
}

// ---------------- GEMM: C = A[M,K] @ W[N,K]^T + bias (opt relu), FFMA2 -------
// 128x128 block tile, 256 threads, 8x8 per-thread tile, double-buffered smem.
// Requires: M%128==0, N%128==0, K%16==0.
#define GBM 128
#define GBN 128
#define GBK 16
__global__ __launch_bounds__(256, 2)
void gemm_bias_kernel(const float* __restrict__ A,
                      const float* __restrict__ W,
                      const float* __restrict__ bias,
                      float* __restrict__ C,
                      int N, int K, int doRelu){
    __shared__ __align__(16) float As[2][GBK][GBM];
    __shared__ __align__(16) float Ws[2][GBK][GBN];
    int tid = threadIdx.x;
    int rowBase = blockIdx.y * GBM;
    int colBase = blockIdx.x * GBN;
    int ty = tid >> 4, tx = tid & 15;      // 16x16 threads, 8x8 outputs each
    int lr = tid >> 1, lk = (tid & 1) * 8; // load: row lr, 8 consecutive k

    const float* Abase = A + (size_t)(rowBase + lr)*K + lk;
    const float* Wbase = W + (size_t)(colBase + lr)*K + lk;

    // preload tile 0 into buffer 0
    float4 pa0 = *(const float4*)(Abase);
    float4 pa1 = *(const float4*)(Abase + 4);
    float4 pw0 = *(const float4*)(Wbase);
    float4 pw1 = *(const float4*)(Wbase + 4);
    As[0][lk+0][lr]=pa0.x; As[0][lk+1][lr]=pa0.y; As[0][lk+2][lr]=pa0.z; As[0][lk+3][lr]=pa0.w;
    As[0][lk+4][lr]=pa1.x; As[0][lk+5][lr]=pa1.y; As[0][lk+6][lr]=pa1.z; As[0][lk+7][lr]=pa1.w;
    Ws[0][lk+0][lr]=pw0.x; Ws[0][lk+1][lr]=pw0.y; Ws[0][lk+2][lr]=pw0.z; Ws[0][lk+3][lr]=pw0.w;
    Ws[0][lk+4][lr]=pw1.x; Ws[0][lk+5][lr]=pw1.y; Ws[0][lk+6][lr]=pw1.z; Ws[0][lk+7][lr]=pw1.w;
    __syncthreads();

    unsigned long long acc[4][8];
#pragma unroll
    for (int i = 0; i < 4; i++)
#pragma unroll
        for (int j = 0; j < 8; j++) acc[i][j] = 0ull;

    int nt = K / GBK;
    for (int t = 0; t < nt; t++) {
        if (t + 1 < nt) {   // prefetch next tile into regs (overlaps compute)
            const float* ap = Abase + (t+1)*GBK;
            const float* wp = Wbase + (t+1)*GBK;
            pa0 = *(const float4*)(ap);
            pa1 = *(const float4*)(ap + 4);
            pw0 = *(const float4*)(wp);
            pw1 = *(const float4*)(wp + 4);
        }
        int cur = t & 1;
#pragma unroll
        for (int k = 0; k < GBK; k++) {
            const double2* ap2 = (const double2*)&As[cur][k][ty*8];
            double2 ad0 = ap2[0], ad1 = ap2[1];
            unsigned long long r0 = dl(ad0.x), r1 = dl(ad0.y);
            unsigned long long r2 = dl(ad1.x), r3 = dl(ad1.y);
            const float4* bp = (const float4*)&Ws[cur][k][tx*8];
            float4 bw0 = bp[0], bw1 = bp[1];
            unsigned long long b0 = pack2(bw0.x), b1 = pack2(bw0.y);
            unsigned long long b2 = pack2(bw0.z), b3 = pack2(bw0.w);
            unsigned long long b4 = pack2(bw1.x), b5 = pack2(bw1.y);
            unsigned long long b6 = pack2(bw1.z), b7 = pack2(bw1.w);
            fma2(acc[0][0], r0, b0); fma2(acc[0][1], r0, b1); fma2(acc[0][2], r0, b2); fma2(acc[0][3], r0, b3);
            fma2(acc[0][4], r0, b4); fma2(acc[0][5], r0, b5); fma2(acc[0][6], r0, b6); fma2(acc[0][7], r0, b7);
            fma2(acc[1][0], r1, b0); fma2(acc[1][1], r1, b1); fma2(acc[1][2], r1, b2); fma2(acc[1][3], r1, b3);
            fma2(acc[1][4], r1, b4); fma2(acc[1][5], r1, b5); fma2(acc[1][6], r1, b6); fma2(acc[1][7], r1, b7);
            fma2(acc[2][0], r2, b0); fma2(acc[2][1], r2, b1); fma2(acc[2][2], r2, b2); fma2(acc[2][3], r2, b3);
            fma2(acc[2][4], r2, b4); fma2(acc[2][5], r2, b5); fma2(acc[2][6], r2, b6); fma2(acc[2][7], r2, b7);
            fma2(acc[3][0], r3, b0); fma2(acc[3][1], r3, b1); fma2(acc[3][2], r3, b2); fma2(acc[3][3], r3, b3);
            fma2(acc[3][4], r3, b4); fma2(acc[3][5], r3, b5); fma2(acc[3][6], r3, b6); fma2(acc[3][7], r3, b7);
        }
        if (t + 1 < nt) {
            int nxt = (t + 1) & 1;
            As[nxt][lk+0][lr]=pa0.x; As[nxt][lk+1][lr]=pa0.y; As[nxt][lk+2][lr]=pa0.z; As[nxt][lk+3][lr]=pa0.w;
            As[nxt][lk+4][lr]=pa1.x; As[nxt][lk+5][lr]=pa1.y; As[nxt][lk+6][lr]=pa1.z; As[nxt][lk+7][lr]=pa1.w;
            Ws[nxt][lk+0][lr]=pw0.x; Ws[nxt][lk+1][lr]=pw0.y; Ws[nxt][lk+2][lr]=pw0.z; Ws[nxt][lk+3][lr]=pw0.w;
            Ws[nxt][lk+4][lr]=pw1.x; Ws[nxt][lk+5][lr]=pw1.y; Ws[nxt][lk+6][lr]=pw1.z; Ws[nxt][lk+7][lr]=pw1.w;
            __syncthreads();
        }
    }

    int c = colBase + tx*8;
    float4 b4a = *(const float4*)(bias + c);
    float4 b4b = *(const float4*)(bias + c + 4);
#pragma unroll
    for (int i2 = 0; i2 < 4; i2++) {
        float2 u0 = unpk2(acc[i2][0]), u1 = unpk2(acc[i2][1]);
        float2 u2 = unpk2(acc[i2][2]), u3 = unpk2(acc[i2][3]);
        float2 u4 = unpk2(acc[i2][4]), u5 = unpk2(acc[i2][5]);
        float2 u6 = unpk2(acc[i2][6]), u7 = unpk2(acc[i2][7]);
        float4 lo0 = make_float4(u0.x+b4a.x, u1.x+b4a.y, u2.x+b4a.z, u3.x+b4a.w);
        float4 lo1 = make_float4(u4.x+b4b.x, u5.x+b4b.y, u6.x+b4b.z, u7.x+b4b.w);
        float4 hi0 = make_float4(u0.y+b4a.x, u1.y+b4a.y, u2.y+b4a.z, u3.y+b4a.w);
        float4 hi1 = make_float4(u4.y+b4b.x, u5.y+b4b.y, u6.y+b4b.z, u7.y+b4b.w);
        if (doRelu) {
            lo0.x=fmaxf(lo0.x,0.f); lo0.y=fmaxf(lo0.y,0.f); lo0.z=fmaxf(lo0.z,0.f); lo0.w=fmaxf(lo0.w,0.f);
            lo1.x=fmaxf(lo1.x,0.f); lo1.y=fmaxf(lo1.y,0.f); lo1.z=fmaxf(lo1.z,0.f); lo1.w=fmaxf(lo1.w,0.f);
            hi0.x=fmaxf(hi0.x,0.f); hi0.y=fmaxf(hi0.y,0.f); hi0.z=fmaxf(hi0.z,0.f); hi0.w=fmaxf(hi0.w,0.f);
            hi1.x=fmaxf(hi1.x,0.f); hi1.y=fmaxf(hi1.y,0.f); hi1.z=fmaxf(hi1.z,0.f); hi1.w=fmaxf(hi1.w,0.f);
        }
        int r0 = rowBase + ty*8 + i2*2;
        *(float4*)(C + (size_t)r0*N + c)         = lo0;
        *(float4*)(C + (size_t)r0*N + c + 4)     = lo1;
        *(float4*)(C + (size_t)(r0+1)*N + c)     = hi0;
        *(float4*)(C + (size_t)(r0+1)*N + c + 4) = hi1;
    }
}

// ---------------- suffix-V sums per (b,h): SV[j] = sum_{t>=j} V[t] -----------
__global__ void svsum_kernel(const float* __restrict__ qkv, float* __restrict__ sv){
    __shared__ float segsum[8][64];
    int bh = blockIdx.x, b = bh >> 3, h = bh & 7;
    const float* vbase = qkv + (size_t)b*Tt*QKVDIM + h*HCH + 2*DH;
    int seg = threadIdx.x >> 6, d = threadIdx.x & 63;
    int j0 = seg * 128;
    float acc = 0.f;
    for (int j = j0; j < j0 + 128; j++) acc += vbase[(size_t)j*QKVDIM + d];
    segsum[seg][d] = acc;
    __syncthreads();
    float tl = 0.f;
    for (int s2 = seg + 1; s2 < 8; s2++) tl += segsum[s2][d];
    float* svb = sv + (size_t)bh*Tt*DH;
    acc = tl;
    for (int j = j0 + 127; j >= j0; j--) {
        acc += vbase[(size_t)j*QKVDIM + d];
        svb[(size_t)j*DH + d] = acc;
    }
}

// ---------------- attention --------------------------------------------------
// tril-multiply semantics: s_j = (q.k_j)*scale for j<=qi, EXACTLY 0 for j>qi,
// softmax over ALL T. No running max: post-LN activations give |s| ~ N(0,1),
// max over all samples ~6; clamp at 80 guards overflow (exp(80)*1024 < FLT_MAX).
// Masked tail: l += (T-1-qi)*exp(0)=count, o += SV[qi+1].
// grid (B*H, T/64), block 256 (4 threads/query), dyn smem 64KB.
#define TJ 128
__global__ void attn_kernel(const float* __restrict__ qkv,
                            const float* __restrict__ sv,
                            float* __restrict__ out){
    extern __shared__ float smem[];
    float* Ks = smem;            // [TJ][64]
    float* Vs = smem + TJ*DH;    // [TJ][64]
    int tid = threadIdx.x;
    int b = blockIdx.x >> 3;
    int h = blockIdx.x & 7;
    const float* base = qkv + (size_t)b*Tt*QKVDIM + h*HCH;

    int qLocal  = tid >> 2;
    int quarter = tid & 3;
    int qi = blockIdx.y * 64 + qLocal;
    int lane = tid & 31;
    unsigned grpmask = 0xFu << (lane & 28);
    int qiWarpMax = blockIdx.y * 64 + ((tid >> 5) << 3) + 7;
    const float scale = 0.125f;      // 1/sqrt(64)

    unsigned long long qp[8];
    {
        const double2* qd = (const double2*)(base + (size_t)qi*QKVDIM + quarter*16);
        double2 d0 = qd[0], d1 = qd[1], d2 = qd[2], d3 = qd[3];
        qp[0]=dl(d0.x); qp[1]=dl(d0.y); qp[2]=dl(d1.x); qp[3]=dl(d1.y);
        qp[4]=dl(d2.x); qp[5]=dl(d2.y); qp[6]=dl(d3.x); qp[7]=dl(d3.y);
    }

    float l = 0.f;
    unsigned long long o[8];
#pragma unroll
    for (int i = 0; i < 8; i++) o[i] = 0ull;

    int jmaxBlock = blockIdx.y * 64 + 63;
    for (int j0 = 0; j0 <= jmaxBlock; j0 += TJ) {
        for (int i = tid; i < TJ*16; i += 256) {
            int r = i >> 4, f = (i & 15) << 2;
            const float* rowp = base + (size_t)(j0 + r)*QKVDIM;
            *(float4*)(Ks + r*DH + f) = *(const float4*)(rowp + DH   + f);
            *(float4*)(Vs + r*DH + f) = *(const float4*)(rowp + 2*DH + f);
        }
        __syncthreads();

        int jlim = min(TJ, qiWarpMax - j0 + 1);   // warp-uniform
        for (int j = 0; j < jlim; j++) {
            int jj = j0 + j;
            if (jj <= qi) {                        // uniform across 4-lane group
                const double2* kd = (const double2*)(Ks + j*DH + quarter*16);
                double2 k0 = kd[0], k1 = kd[1], k2 = kd[2], k3 = kd[3];
                unsigned long long d0 = 0ull, d1 = 0ull;
                d0 = fma2v(qp[0], dl(k0.x), d0); d1 = fma2v(qp[1], dl(k0.y), d1);
                d0 = fma2v(qp[2], dl(k1.x), d0); d1 = fma2v(qp[3], dl(k1.y), d1);
                d0 = fma2v(qp[4], dl(k2.x), d0); d1 = fma2v(qp[5], dl(k2.y), d1);
                d0 = fma2v(qp[6], dl(k3.x), d0); d1 = fma2v(qp[7], dl(k3.y), d1);
                float2 ds = unpk2(add2(d0, d1));
                float s = ds.x + ds.y;
                s += __shfl_xor_sync(grpmask, s, 1);
                s += __shfl_xor_sync(grpmask, s, 2);
                float p = __expf(fminf(s * scale, 80.f));
                l += p;
                unsigned long long pp = pack2(p);
                const double2* vd = (const double2*)(Vs + j*DH + quarter*16);
                double2 v0 = vd[0], v1 = vd[1], v2 = vd[2], v3 = vd[3];
                o[0] = fma2v(pp, dl(v0.x), o[0]);
                o[1] = fma2v(pp, dl(v0.y), o[1]);
                o[2] = fma2v(pp, dl(v1.x), o[2]);
                o[3] = fma2v(pp, dl(v1.y), o[3]);
                o[4] = fma2v(pp, dl(v2.x), o[4]);
                o[5] = fma2v(pp, dl(v2.y), o[5]);
                o[6] = fma2v(pp, dl(v3.x), o[6]);
                o[7] = fma2v(pp, dl(v3.y), o[7]);
            }
        }
        __syncthreads();
    }

    // analytic masked tail: each masked j contributes exp(0)=1 and 1*V[j]
    if (qi < Tt - 1) {
        l += (float)(Tt - 1 - qi);
        const double2* svd = (const double2*)(sv + ((size_t)blockIdx.x*Tt + (qi+1))*DH + quarter*16);
        double2 s0 = svd[0], s1 = svd[1], s2 = svd[2], s3 = svd[3];
        o[0] = add2(o[0], dl(s0.x));
        o[1] = add2(o[1], dl(s0.y));
        o[2] = add2(o[2], dl(s1.x));
        o[3] = add2(o[3], dl(s1.y));
        o[4] = add2(o[4], dl(s2.x));
        o[5] = add2(o[5], dl(s2.y));
        o[6] = add2(o[6], dl(s3.x));
        o[7] = add2(o[7], dl(s3.y));
    }

    float inv = 1.f / l;
    unsigned long long ip = pack2(inv);
    float2 u0 = unpk2(mul2(o[0], ip)), u1 = unpk2(mul2(o[1], ip));
    float2 u2 = unpk2(mul2(o[2], ip)), u3 = unpk2(mul2(o[3], ip));
    float2 u4 = unpk2(mul2(o[4], ip)), u5 = unpk2(mul2(o[5], ip));
    float2 u6 = unpk2(mul2(o[6], ip)), u7 = unpk2(mul2(o[7], ip));
    float* op = out + ((size_t)b*Tt + qi)*Ee + h*DH + quarter*16;
    *(float4*)(op +  0) = make_float4(u0.x, u0.y, u1.x, u1.y);
    *(float4*)(op +  4) = make_float4(u2.x, u2.y, u3.x, u3.y);
    *(float4*)(op +  8) = make_float4(u4.x, u4.y, u5.x, u5.y);
    *(float4*)(op + 12) = make_float4(u6.x, u6.y, u7.x, u7.y);
}

// ---------------- fused residual-add + LayerNorm (warp per row, E=512) -------
__global__ void add_ln_kernel(const float* __restrict__ a, const float* __restrict__ b,
                              const float* __restrict__ gam, const float* __restrict__ bet,
                              float* __restrict__ out){
    int warp = threadIdx.x >> 5, lane = threadIdx.x & 31;
    int row = blockIdx.x * 8 + warp;
    size_t rb = (size_t)row*Ee;
    float xs[16];
    float sum = 0.f, sq = 0.f;
#pragma unroll
    for (int c = 0; c < 4; c++) {
        size_t off = rb + c*128 + lane*4;
        float4 va = *(const float4*)(a + off);
        float4 vb = *(const float4*)(b + off);
        float x0 = va.x+vb.x, x1 = va.y+vb.y, x2 = va.z+vb.z, x3 = va.w+vb.w;
        xs[c*4+0]=x0; xs[c*4+1]=x1; xs[c*4+2]=x2; xs[c*4+3]=x3;
        sum += x0+x1+x2+x3;
        sq  += x0*x0+x1*x1+x2*x2+x3*x3;
    }
    sum = warp_sum(sum);
    sq  = warp_sum(sq);
    float mean = sum * (1.f/(float)Ee);
    float var  = sq  * (1.f/(float)Ee) - mean*mean;
    float r = rsqrtf(var + 1e-5f);
#pragma unroll
    for (int c = 0; c < 4; c++) {
        int col = c*128 + lane*4;
        float4 g  = *(const float4*)(gam + col);
        float4 be = *(const float4*)(bet + col);
        *(float4*)(out + rb + col) = make_float4(
            (xs[c*4+0]-mean)*r*g.x + be.x,
            (xs[c*4+1]-mean)*r*g.y + be.y,
            (xs[c*4+2]-mean)*r*g.z + be.z,
            (xs[c*4+3]-mean)*r*g.w + be.w);
    }
}

// ---------------- loss: per-row smoothed CE, deterministic 2-stage reduce ----
__global__ void loss_rows_kernel(const float* __restrict__ logits,
                                 const void* __restrict__ tgt,
                                 float* __restrict__ partials){
    __shared__ float rvals[8];
    int warp = threadIdx.x >> 5, lane = threadIdx.x & 31;
    int row = blockIdx.x * 8 + warp;
    const float* lp = logits + (size_t)row*Vv;
    float4 v = *(const float4*)(lp + lane*4);
    float mx = warp_max(fmaxf(fmaxf(v.x, v.y), fmaxf(v.z, v.w)));
    float sm = warp_sum(v.x + v.y + v.z + v.w);
    float se = warp_sum(__expf(v.x-mx) + __expf(v.y-mx) + __expf(v.z-mx) + __expf(v.w-mx));
    if (lane == 0) {
        float logZ = mx + logf(se);
        int t = get_tok(tgt, row);
        float nll    = logZ - lp[t];
        float smooth = logZ - sm * (1.f/(float)Vv);
        rvals[warp] = 0.9f*nll + 0.1f*smooth;
    }
    __syncthreads();
    if (threadIdx.x == 0) {
        float s = 0.f;
        for (int i = 0; i < 8; i++) s += rvals[i];
        partials[blockIdx.x] = s;
    }
}

__global__ void loss_final_kernel(const float* __restrict__ partials, float* __restrict__ out){
    __shared__ float s[512];
    int tid = threadIdx.x;
    s[tid] = partials[tid];
    __syncthreads();
    for (int o = 256; o; o >>= 1) {
        if (tid < o) s[tid] += s[tid + o];
        __syncthreads();
    }
    if (tid == 0) out[0] = s[0] * (1.f/(float)NTOK);
}

// ---------------- launch ------------------------------------------------------
extern "C" void kernel_launch(void* const* d_in, const int* in_sizes, int n_in,
                              void* d_out, int out_size){
    const void *inputs, *targets;
    const float *emb, *qkv_w, *qkv_b, *aff1_w, *aff1_b, *aff2_w, *aff2_b;
    const float *ffn1_w, *ffn1_b, *ffn2_w, *ffn2_b;
    const float *ln1_s, *ln1_b, *ln2_s, *ln2_b, *head_w, *head_b;

    if (in_sizes[1] > 100000) {
        // alphabetical ordering
        aff1_b = (const float*)d_in[0];
        aff1_w = (const float*)d_in[1];
        aff2_b = (const float*)d_in[2];
        aff2_w = (const float*)d_in[3];
        emb    = (const float*)d_in[4];
        ffn1_b = (const float*)d_in[5];
        ffn1_w = (const float*)d_in[6];
        ffn2_b = (const float*)d_in[7];
        ffn2_w = (const float*)d_in[8];
        head_b = (const float*)d_in[9];
        head_w = (const float*)d_in[10];
        inputs = d_in[11];
        ln1_b  = (const float*)d_in[12];
        ln1_s  = (const float*)d_in[13];
        ln2_b  = (const float*)d_in[14];
        ln2_s  = (const float*)d_in[15];
        qkv_b  = (const float*)d_in[16];
        qkv_w  = (const float*)d_in[17];
        targets= d_in[18];
    } else {
        // signature / insertion ordering
        inputs  = d_in[0];
        targets = d_in[1];
        emb     = (const float*)d_in[2];
        qkv_w   = (const float*)d_in[3];
        qkv_b   = (const float*)d_in[4];
        aff1_w  = (const float*)d_in[5];
        aff1_b  = (const float*)d_in[6];
        aff2_w  = (const float*)d_in[7];
        aff2_b  = (const float*)d_in[8];
        ffn1_w  = (const float*)d_in[9];
        ffn1_b  = (const float*)d_in[10];
        ffn2_w  = (const float*)d_in[11];
        ffn2_b  = (const float*)d_in[12];
        ln1_s   = (const float*)d_in[13];
        ln1_b   = (const float*)d_in[14];
        ln2_s   = (const float*)d_in[15];
        ln2_b   = (const float*)d_in[16];
        head_w  = (const float*)d_in[17];
        head_b  = (const float*)d_in[18];
    }
    float* out = (float*)d_out;

    float *x, *qkv, *att, *tmp, *aff, *out1, *sv, *logits_scratch, *partials;
    cudaGetSymbolAddress((void**)&x,    g_x);
    cudaGetSymbolAddress((void**)&qkv,  g_qkv);
    cudaGetSymbolAddress((void**)&att,  g_att);
    cudaGetSymbolAddress((void**)&tmp,  g_tmp);
    cudaGetSymbolAddress((void**)&aff,  g_aff);
    cudaGetSymbolAddress((void**)&out1, g_out1);
    cudaGetSymbolAddress((void**)&sv,   g_sv);
    cudaGetSymbolAddress((void**)&logits_scratch, g_logits);
    cudaGetSymbolAddress((void**)&partials, g_partials);

    const int BTV = NTOK * Vv;                      // 524288
    float* logits_dst = (out_size >= BTV) ? out : logits_scratch;
    float* loss_dst   = (out_size > BTV) ? (out + BTV)
                       : ((out_size > 0 && out_size < BTV) ? out : nullptr);

    const int ATTN_SMEM = 2 * TJ * DH * (int)sizeof(float);  // 65536
    cudaFuncSetAttribute(attn_kernel, cudaFuncAttributeMaxDynamicSharedMemorySize, ATTN_SMEM);

    detect_kernel<<<1, 1>>>((const int*)inputs);
    embed_kernel<<<NTOK, 128>>>(inputs, emb, x);

    dim3 gQKV(QKVDIM/GBN, NTOK/GBM);  // (12,32)
    dim3 gE  (Ee/GBN,     NTOK/GBM);  // (4,32)
    dim3 gHead(Vv/GBN,    NTOK/GBM);  // (1,32)
    dim3 gAtt(Bsz*Hh, Tt/64);         // (32,16)

    for (int l = 0; l < Ll; l++) {
        gemm_bias_kernel<<<gQKV, 256>>>(x, qkv_w + (size_t)l*QKVDIM*Ee, qkv_b + (size_t)l*QKVDIM, qkv, QKVDIM, Ee, 0);
        svsum_kernel<<<Bsz*Hh, 512>>>(qkv, sv);
        attn_kernel<<<gAtt, 256, ATTN_SMEM>>>(qkv, sv, att);
        gemm_bias_kernel<<<gE, 256>>>(att, aff1_w + (size_t)l*Ee*Ee, aff1_b + (size_t)l*Ee, tmp, Ee, Ee, 1);
        gemm_bias_kernel<<<gE, 256>>>(tmp, aff2_w + (size_t)l*Ee*Ee, aff2_b + (size_t)l*Ee, aff, Ee, Ee, 0);
        add_ln_kernel<<<NTOK/8, 256>>>(aff, x, ln1_s + (size_t)l*Ee, ln1_b + (size_t)l*Ee, out1);
        gemm_bias_kernel<<<gE, 256>>>(out1, ffn1_w + (size_t)l*Ee*Ee, ffn1_b + (size_t)l*Ee, tmp, Ee, Ee, 1);
        gemm_bias_kernel<<<gE, 256>>>(tmp, ffn2_w + (size_t)l*Ee*Ee, ffn2_b + (size_t)l*Ee, aff, Ee, Ee, 0);
        add_ln_kernel<<<NTOK/8, 256>>>(out1, aff, ln2_s + (size_t)l*Ee, ln2_b + (size_t)l*Ee, x);
    }

    gemm_bias_kernel<<<gHead, 256>>>(x, head_w, head_b, logits_dst, Vv, Ee, 0);
    loss_rows_kernel<<<NTOK/8, 256>>>(logits_dst, targets, partials);
    if (loss_dst)
        loss_final_kernel<<<1, 512>>>(partials, loss_dst);
}

// round 10
// speedup vs baseline: 2.2274x; 1.2243x over previous
#include <cuda_runtime.h>
#include <cuda_bf16.h>
#include <cuda_fp16.h>
#include <cstdint>

// Problem constants (V,E,L,H = 128,512,8,8; B,T = 4,1024)
#define Bsz 4
#define Tt  1024
#define Vv  128
#define Ee  512
#define Hh  8
#define Ll  8
#define DH  64
#define NTOK (Bsz*Tt)          // 4096
#define QKVDIM (3*Ee)          // 1536
#define HCH (3*DH)             // 192

// ---------------- scratch (device globals; no allocation allowed) -----------
__device__ float g_x   [NTOK*Ee];
__device__ float g_qkv [NTOK*QKVDIM];
__device__ float g_att [NTOK*Ee];
__device__ float g_tmp [NTOK*Ee];
__device__ float g_aff [NTOK*Ee];
__device__ float g_out1[NTOK*Ee];
__device__ float g_sv  [Bsz*Hh*Tt*DH];
__device__ float g_logits[NTOK*Vv];
__device__ float g_partials[512];
__device__ int   g_is32;

extern __shared__ __align__(1024) char dynsmem[];

// ---------------- f32x2 helpers (used by attention) ---------------------------
__device__ __forceinline__ unsigned long long dl(double d){ return __double_as_longlong(d); }
__device__ __forceinline__ unsigned long long pack2(float x){
    unsigned long long r; asm("mov.b64 %0, {%1, %1};" : "=l"(r) : "f"(x)); return r;
}
__device__ __forceinline__ unsigned long long fma2v(unsigned long long a, unsigned long long b, unsigned long long c){
    unsigned long long d; asm("fma.rn.f32x2 %0, %1, %2, %3;" : "=l"(d) : "l"(a), "l"(b), "l"(c)); return d;
}
__device__ __forceinline__ unsigned long long mul2(unsigned long long a, unsigned long long b){
    unsigned long long d; asm("mul.rn.f32x2 %0, %1, %2;" : "=l"(d) : "l"(a), "l"(b)); return d;
}
__device__ __forceinline__ unsigned long long add2(unsigned long long a, unsigned long long b){
    unsigned long long d; asm("add.rn.f32x2 %0, %1, %2;" : "=l"(d) : "l"(a), "l"(b)); return d;
}
__device__ __forceinline__ float2 unpk2(unsigned long long v){
    float lo, hi; asm("mov.b64 {%0, %1}, %2;" : "=f"(lo), "=f"(hi) : "l"(v)); return make_float2(lo, hi);
}

// ---------------- misc helpers -----------------------------------------------
__device__ __forceinline__ float warp_sum(float v){
#pragma unroll
    for (int o = 16; o; o >>= 1) v += __shfl_xor_sync(0xffffffffu, v, o);
    return v;
}
__device__ __forceinline__ float warp_max(float v){
#pragma unroll
    for (int o = 16; o; o >>= 1) v = fmaxf(v, __shfl_xor_sync(0xffffffffu, v, o));
    return v;
}
__device__ __forceinline__ int get_tok(const void* p, int i){
    return g_is32 ? ((const int*)p)[i] : (int)((const long long*)p)[i];
}

__global__ void detect_kernel(const int* __restrict__ inp){
    int is32 = 0;
    for (int i = 1; i < 128; i += 2) if (inp[i] != 0) { is32 = 1; break; }
    g_is32 = is32;
}

// ---------------- embedding --------------------------------------------------
__global__ void embed_kernel(const void* __restrict__ inp,
                             const float* __restrict__ emb,
                             float* __restrict__ x){
    int t = blockIdx.x;
    int tok = get_tok(inp, t);
    *(float4*)(x + (size_t)t*Ee + threadIdx.x*4) =
        *(const float4*)(emb + (size_t)tok*Ee + threadIdx.x*4);
}

// ================= fp16 split-precision mma.sync GEMM =========================
// C[M,N] = A[M,K] @ W[N,K]^T + bias (opt relu). fp32 in/out.
// a = ah + al (fp16 each); D = Ah*Wh + Ah*Wl + Al*Wh, fp32 accum (HMMA).
// Block 128x128, 256 threads = 8 warps (2x4), warp tile 64x32 (4x4 m16n8k16).
// K chunks of 32, double-buffered smem + register prefetch, 1 sync/chunk.
#define KC 32
#define SSTR 40                        // padded half-stride per row
#define TILEH (128*SSTR)               // halves per tensor-buffer (5120)
#define GEMM_SMEM_BYTES (2*4*TILEH*2)  // 81920

__device__ __forceinline__ void mma16816(float* c, const uint32_t* a, const uint32_t* b){
    asm volatile("mma.sync.aligned.m16n8k16.row.col.f32.f16.f16.f32 "
        "{%0,%1,%2,%3}, {%4,%5,%6,%7}, {%8,%9}, {%0,%1,%2,%3};"
        : "+f"(c[0]), "+f"(c[1]), "+f"(c[2]), "+f"(c[3])
        : "r"(a[0]), "r"(a[1]), "r"(a[2]), "r"(a[3]), "r"(b[0]), "r"(b[1]));
}

// convert float4 (k..k+3) to hi/lo half pairs and store into padded smem row
__device__ __forceinline__ void cvt_store4(__half* dstH, __half* dstL, int hidx, float4 v){
    __half h0 = __float2half_rn(v.x), h1 = __float2half_rn(v.y);
    __half h2 = __float2half_rn(v.z), h3 = __float2half_rn(v.w);
    __half l0 = __float2half_rn(v.x - __half2float(h0));
    __half l1 = __float2half_rn(v.y - __half2float(h1));
    __half l2 = __float2half_rn(v.z - __half2float(h2));
    __half l3 = __float2half_rn(v.w - __half2float(h3));
    *(__half2*)(dstH + hidx)     = __halves2half2(h0, h1);
    *(__half2*)(dstH + hidx + 2) = __halves2half2(h2, h3);
    *(__half2*)(dstL + hidx)     = __halves2half2(l0, l1);
    *(__half2*)(dstL + hidx + 2) = __halves2half2(l2, l3);
}

__global__ __launch_bounds__(256, 1)
void gemm_tc_kernel(const float* __restrict__ A,
                    const float* __restrict__ W,
                    const float* __restrict__ bias,
                    float* __restrict__ C,
                    int N, int K, int doRelu){
    __half* sm = (__half*)dynsmem;
    int tid = threadIdx.x, wid = tid >> 5, lane = tid & 31;
    int warpM = wid >> 2, warpN = wid & 3;
    int rowBase = blockIdx.y * 128, colBase = blockIdx.x * 128;

    // staging coords: each thread stages 16 consecutive k of one row (A and W)
    int srow = tid >> 1;
    int skq  = (tid & 1) * 16;
    const float* aSrc = A + (size_t)(rowBase + srow)*K + skq;
    const float* wSrc = W + (size_t)(colBase + srow)*K + skq;

    float acc[4][4][4];
#pragma unroll
    for (int i = 0; i < 4; i++)
#pragma unroll
        for (int j = 0; j < 4; j++)
#pragma unroll
            for (int q = 0; q < 4; q++) acc[i][j][q] = 0.f;

    // prologue: load + stage chunk 0 into buffer 0
    float4 af[4], wf[4];
#pragma unroll
    for (int i = 0; i < 4; i++){
        af[i] = *(const float4*)(aSrc + i*4);
        wf[i] = *(const float4*)(wSrc + i*4);
    }
    {
        __half* Ah = sm;            __half* Al = Ah + TILEH;
        __half* Wh = Al + TILEH;    __half* Wl = Wh + TILEH;
        int base = srow*SSTR + skq;
#pragma unroll
        for (int i = 0; i < 4; i++){
            cvt_store4(Ah, Al, base + i*4, af[i]);
            cvt_store4(Wh, Wl, base + i*4, wf[i]);
        }
    }
    __syncthreads();

    int r  = lane >> 2;
    int cp = (lane & 3) * 2;
    int nch = K / KC;

    for (int c = 0; c < nch; c++){
        if (c + 1 < nch){
            const float* ap = aSrc + (c+1)*KC;
            const float* wp = wSrc + (c+1)*KC;
#pragma unroll
            for (int i = 0; i < 4; i++){
                af[i] = *(const float4*)(ap + i*4);
                wf[i] = *(const float4*)(wp + i*4);
            }
        }
        __half* Ah = sm + (c & 1)*4*TILEH;
        __half* Al = Ah + TILEH;
        __half* Wh = Al + TILEH;
        __half* Wl = Wh + TILEH;

#pragma unroll
        for (int ks = 0; ks < 2; ks++){
            int kk = ks * 16;
            uint32_t ah[4][4], al[4][4], bh[4][2], bl[4][2];
#pragma unroll
            for (int mt = 0; mt < 4; mt++){
                int row = warpM*64 + mt*16 + r;
                int i0 = row*SSTR + kk + cp;
                int i8 = (row+8)*SSTR + kk + cp;
                ah[mt][0] = *(const uint32_t*)(Ah + i0);
                ah[mt][1] = *(const uint32_t*)(Ah + i8);
                ah[mt][2] = *(const uint32_t*)(Ah + i0 + 8);
                ah[mt][3] = *(const uint32_t*)(Ah + i8 + 8);
                al[mt][0] = *(const uint32_t*)(Al + i0);
                al[mt][1] = *(const uint32_t*)(Al + i8);
                al[mt][2] = *(const uint32_t*)(Al + i0 + 8);
                al[mt][3] = *(const uint32_t*)(Al + i8 + 8);
            }
#pragma unroll
            for (int nt = 0; nt < 4; nt++){
                int nrow = warpN*32 + nt*8 + r;
                int j0 = nrow*SSTR + kk + cp;
                bh[nt][0] = *(const uint32_t*)(Wh + j0);
                bh[nt][1] = *(const uint32_t*)(Wh + j0 + 8);
                bl[nt][0] = *(const uint32_t*)(Wl + j0);
                bl[nt][1] = *(const uint32_t*)(Wl + j0 + 8);
            }
#pragma unroll
            for (int mt = 0; mt < 4; mt++)
#pragma unroll
                for (int nt = 0; nt < 4; nt++){
                    mma16816(acc[mt][nt], ah[mt], bh[nt]);
                    mma16816(acc[mt][nt], ah[mt], bl[nt]);
                    mma16816(acc[mt][nt], al[mt], bh[nt]);
                }
        }

        if (c + 1 < nch){
            __half* nAh = sm + ((c+1) & 1)*4*TILEH;
            __half* nAl = nAh + TILEH;
            __half* nWh = nAl + TILEH;
            __half* nWl = nWh + TILEH;
            int base = srow*SSTR + skq;
#pragma unroll
            for (int i = 0; i < 4; i++){
                cvt_store4(nAh, nAl, base + i*4, af[i]);
                cvt_store4(nWh, nWl, base + i*4, wf[i]);
            }
            __syncthreads();
        }
    }

    // epilogue: bias + optional relu, direct fp32 stores
#pragma unroll
    for (int mt = 0; mt < 4; mt++){
        int r0 = rowBase + warpM*64 + mt*16 + r;
#pragma unroll
        for (int nt = 0; nt < 4; nt++){
            int c0 = colBase + warpN*32 + nt*8 + cp;
            float b0 = bias[c0], b1 = bias[c0+1];
            float v0 = acc[mt][nt][0] + b0, v1 = acc[mt][nt][1] + b1;
            float v2 = acc[mt][nt][2] + b0, v3 = acc[mt][nt][3] + b1;
            if (doRelu){
                v0 = fmaxf(v0, 0.f); v1 = fmaxf(v1, 0.f);
                v2 = fmaxf(v2, 0.f); v3 = fmaxf(v3, 0.f);
            }
            *(float2*)(C + (size_t)r0*N + c0)     = make_float2(v0, v1);
            *(float2*)(C + (size_t)(r0+8)*N + c0) = make_float2(v2, v3);
        }
    }
}

// ---------------- suffix-V sums per (b,h): SV[j] = sum_{t>=j} V[t] -----------
__global__ void svsum_kernel(const float* __restrict__ qkv, float* __restrict__ sv){
    __shared__ float segsum[8][64];
    int bh = blockIdx.x, b = bh >> 3, h = bh & 7;
    const float* vbase = qkv + (size_t)b*Tt*QKVDIM + h*HCH + 2*DH;
    int seg = threadIdx.x >> 6, d = threadIdx.x & 63;
    int j0 = seg * 128;
    float acc = 0.f;
    for (int j = j0; j < j0 + 128; j++) acc += vbase[(size_t)j*QKVDIM + d];
    segsum[seg][d] = acc;
    __syncthreads();
    float tl = 0.f;
    for (int s2 = seg + 1; s2 < 8; s2++) tl += segsum[s2][d];
    float* svb = sv + (size_t)bh*Tt*DH;
    acc = tl;
    for (int j = j0 + 127; j >= j0; j--) {
        acc += vbase[(size_t)j*QKVDIM + d];
        svb[(size_t)j*DH + d] = acc;
    }
}

// ---------------- attention (validated R7 version) ----------------------------
// tril-multiply semantics: s_j = (q.k_j)*scale for j<=qi, EXACTLY 0 for j>qi,
// softmax over ALL T. No running max (post-LN scores small; clamp guards).
// Masked tail: l += (T-1-qi), o += SV[qi+1].
#define TJ 128
__global__ void attn_kernel(const float* __restrict__ qkv,
                            const float* __restrict__ sv,
                            float* __restrict__ out){
    float* smemf = (float*)dynsmem;
    float* Ks = smemf;
    float* Vs = smemf + TJ*DH;
    int tid = threadIdx.x;
    int b = blockIdx.x >> 3;
    int h = blockIdx.x & 7;
    const float* base = qkv + (size_t)b*Tt*QKVDIM + h*HCH;

    int qLocal  = tid >> 2;
    int quarter = tid & 3;
    int qi = blockIdx.y * 64 + qLocal;
    int lane = tid & 31;
    unsigned grpmask = 0xFu << (lane & 28);
    int qiWarpMax = blockIdx.y * 64 + ((tid >> 5) << 3) + 7;
    const float scale = 0.125f;

    unsigned long long qp[8];
    {
        const double2* qd = (const double2*)(base + (size_t)qi*QKVDIM + quarter*16);
        double2 d0 = qd[0], d1 = qd[1], d2 = qd[2], d3 = qd[3];
        qp[0]=dl(d0.x); qp[1]=dl(d0.y); qp[2]=dl(d1.x); qp[3]=dl(d1.y);
        qp[4]=dl(d2.x); qp[5]=dl(d2.y); qp[6]=dl(d3.x); qp[7]=dl(d3.y);
    }

    float l = 0.f;
    unsigned long long o[8];
#pragma unroll
    for (int i = 0; i < 8; i++) o[i] = 0ull;

    int jmaxBlock = blockIdx.y * 64 + 63;
    for (int j0 = 0; j0 <= jmaxBlock; j0 += TJ) {
        for (int i = tid; i < TJ*16; i += 256) {
            int rr = i >> 4, f = (i & 15) << 2;
            const float* rowp = base + (size_t)(j0 + rr)*QKVDIM;
            *(float4*)(Ks + rr*DH + f) = *(const float4*)(rowp + DH   + f);
            *(float4*)(Vs + rr*DH + f) = *(const float4*)(rowp + 2*DH + f);
        }
        __syncthreads();

        int jlim = min(TJ, qiWarpMax - j0 + 1);
        for (int j = 0; j < jlim; j++) {
            int jj = j0 + j;
            if (jj <= qi) {
                const double2* kd = (const double2*)(Ks + j*DH + quarter*16);
                double2 k0 = kd[0], k1 = kd[1], k2 = kd[2], k3 = kd[3];
                unsigned long long d0 = 0ull, d1 = 0ull;
                d0 = fma2v(qp[0], dl(k0.x), d0); d1 = fma2v(qp[1], dl(k0.y), d1);
                d0 = fma2v(qp[2], dl(k1.x), d0); d1 = fma2v(qp[3], dl(k1.y), d1);
                d0 = fma2v(qp[4], dl(k2.x), d0); d1 = fma2v(qp[5], dl(k2.y), d1);
                d0 = fma2v(qp[6], dl(k3.x), d0); d1 = fma2v(qp[7], dl(k3.y), d1);
                float2 ds = unpk2(add2(d0, d1));
                float s = ds.x + ds.y;
                s += __shfl_xor_sync(grpmask, s, 1);
                s += __shfl_xor_sync(grpmask, s, 2);
                float p = __expf(fminf(s * scale, 80.f));
                l += p;
                unsigned long long pp = pack2(p);
                const double2* vd = (const double2*)(Vs + j*DH + quarter*16);
                double2 v0 = vd[0], v1 = vd[1], v2 = vd[2], v3 = vd[3];
                o[0] = fma2v(pp, dl(v0.x), o[0]);
                o[1] = fma2v(pp, dl(v0.y), o[1]);
                o[2] = fma2v(pp, dl(v1.x), o[2]);
                o[3] = fma2v(pp, dl(v1.y), o[3]);
                o[4] = fma2v(pp, dl(v2.x), o[4]);
                o[5] = fma2v(pp, dl(v2.y), o[5]);
                o[6] = fma2v(pp, dl(v3.x), o[6]);
                o[7] = fma2v(pp, dl(v3.y), o[7]);
            }
        }
        __syncthreads();
    }

    if (qi < Tt - 1) {
        l += (float)(Tt - 1 - qi);
        const double2* svd = (const double2*)(sv + ((size_t)blockIdx.x*Tt + (qi+1))*DH + quarter*16);
        double2 s0 = svd[0], s1 = svd[1], s2 = svd[2], s3 = svd[3];
        o[0] = add2(o[0], dl(s0.x));
        o[1] = add2(o[1], dl(s0.y));
        o[2] = add2(o[2], dl(s1.x));
        o[3] = add2(o[3], dl(s1.y));
        o[4] = add2(o[4], dl(s2.x));
        o[5] = add2(o[5], dl(s2.y));
        o[6] = add2(o[6], dl(s3.x));
        o[7] = add2(o[7], dl(s3.y));
    }

    float inv = 1.f / l;
    unsigned long long ip = pack2(inv);
    float2 u0 = unpk2(mul2(o[0], ip)), u1 = unpk2(mul2(o[1], ip));
    float2 u2 = unpk2(mul2(o[2], ip)), u3 = unpk2(mul2(o[3], ip));
    float2 u4 = unpk2(mul2(o[4], ip)), u5 = unpk2(mul2(o[5], ip));
    float2 u6 = unpk2(mul2(o[6], ip)), u7 = unpk2(mul2(o[7], ip));
    float* op = out + ((size_t)b*Tt + qi)*Ee + h*DH + quarter*16;
    *(float4*)(op +  0) = make_float4(u0.x, u0.y, u1.x, u1.y);
    *(float4*)(op +  4) = make_float4(u2.x, u2.y, u3.x, u3.y);
    *(float4*)(op +  8) = make_float4(u4.x, u4.y, u5.x, u5.y);
    *(float4*)(op + 12) = make_float4(u6.x, u6.y, u7.x, u7.y);
}

// ---------------- fused residual-add + LayerNorm (warp per row, E=512) -------
__global__ void add_ln_kernel(const float* __restrict__ a, const float* __restrict__ b,
                              const float* __restrict__ gam, const float* __restrict__ bet,
                              float* __restrict__ out){
    int warp = threadIdx.x >> 5, lane = threadIdx.x & 31;
    int row = blockIdx.x * 8 + warp;
    size_t rb = (size_t)row*Ee;
    float xs[16];
    float sum = 0.f, sq = 0.f;
#pragma unroll
    for (int c = 0; c < 4; c++) {
        size_t off = rb + c*128 + lane*4;
        float4 va = *(const float4*)(a + off);
        float4 vb = *(const float4*)(b + off);
        float x0 = va.x+vb.x, x1 = va.y+vb.y, x2 = va.z+vb.z, x3 = va.w+vb.w;
        xs[c*4+0]=x0; xs[c*4+1]=x1; xs[c*4+2]=x2; xs[c*4+3]=x3;
        sum += x0+x1+x2+x3;
        sq  += x0*x0+x1*x1+x2*x2+x3*x3;
    }
    sum = warp_sum(sum);
    sq  = warp_sum(sq);
    float mean = sum * (1.f/(float)Ee);
    float var  = sq  * (1.f/(float)Ee) - mean*mean;
    float r = rsqrtf(var + 1e-5f);
#pragma unroll
    for (int c = 0; c < 4; c++) {
        int col = c*128 + lane*4;
        float4 g  = *(const float4*)(gam + col);
        float4 be = *(const float4*)(bet + col);
        *(float4*)(out + rb + col) = make_float4(
            (xs[c*4+0]-mean)*r*g.x + be.x,
            (xs[c*4+1]-mean)*r*g.y + be.y,
            (xs[c*4+2]-mean)*r*g.z + be.z,
            (xs[c*4+3]-mean)*r*g.w + be.w);
    }
}

// ---------------- loss -------------------------------------------------------
__global__ void loss_rows_kernel(const float* __restrict__ logits,
                                 const void* __restrict__ tgt,
                                 float* __restrict__ partials){
    __shared__ float rvals[8];
    int warp = threadIdx.x >> 5, lane = threadIdx.x & 31;
    int row = blockIdx.x * 8 + warp;
    const float* lp = logits + (size_t)row*Vv;
    float4 v = *(const float4*)(lp + lane*4);
    float mx = warp_max(fmaxf(fmaxf(v.x, v.y), fmaxf(v.z, v.w)));
    float sm = warp_sum(v.x + v.y + v.z + v.w);
    float se = warp_sum(__expf(v.x-mx) + __expf(v.y-mx) + __expf(v.z-mx) + __expf(v.w-mx));
    if (lane == 0) {
        float logZ = mx + logf(se);
        int t = get_tok(tgt, row);
        float nll    = logZ - lp[t];
        float smooth = logZ - sm * (1.f/(float)Vv);
        rvals[warp] = 0.9f*nll + 0.1f*smooth;
    }
    __syncthreads();
    if (threadIdx.x == 0) {
        float s = 0.f;
        for (int i = 0; i < 8; i++) s += rvals[i];
        partials[blockIdx.x] = s;
    }
}

__global__ void loss_final_kernel(const float* __restrict__ partials, float* __restrict__ out){
    __shared__ float s[512];
    int tid = threadIdx.x;
    s[tid] = partials[tid];
    __syncthreads();
    for (int o = 256; o; o >>= 1) {
        if (tid < o) s[tid] += s[tid + o];
        __syncthreads();
    }
    if (tid == 0) out[0] = s[0] * (1.f/(float)NTOK);
}

// ---------------- launch ------------------------------------------------------
extern "C" void kernel_launch(void* const* d_in, const int* in_sizes, int n_in,
                              void* d_out, int out_size){
    const void *inputs, *targets;
    const float *emb, *qkv_w, *qkv_b, *aff1_w, *aff1_b, *aff2_w, *aff2_b;
    const float *ffn1_w, *ffn1_b, *ffn2_w, *ffn2_b;
    const float *ln1_s, *ln1_b, *ln2_s, *ln2_b, *head_w, *head_b;

    if (in_sizes[1] > 100000) {
        aff1_b = (const float*)d_in[0];
        aff1_w = (const float*)d_in[1];
        aff2_b = (const float*)d_in[2];
        aff2_w = (const float*)d_in[3];
        emb    = (const float*)d_in[4];
        ffn1_b = (const float*)d_in[5];
        ffn1_w = (const float*)d_in[6];
        ffn2_b = (const float*)d_in[7];
        ffn2_w = (const float*)d_in[8];
        head_b = (const float*)d_in[9];
        head_w = (const float*)d_in[10];
        inputs = d_in[11];
        ln1_b  = (const float*)d_in[12];
        ln1_s  = (const float*)d_in[13];
        ln2_b  = (const float*)d_in[14];
        ln2_s  = (const float*)d_in[15];
        qkv_b  = (const float*)d_in[16];
        qkv_w  = (const float*)d_in[17];
        targets= d_in[18];
    } else {
        inputs  = d_in[0];
        targets = d_in[1];
        emb     = (const float*)d_in[2];
        qkv_w   = (const float*)d_in[3];
        qkv_b   = (const float*)d_in[4];
        aff1_w  = (const float*)d_in[5];
        aff1_b  = (const float*)d_in[6];
        aff2_w  = (const float*)d_in[7];
        aff2_b  = (const float*)d_in[8];
        ffn1_w  = (const float*)d_in[9];
        ffn1_b  = (const float*)d_in[10];
        ffn2_w  = (const float*)d_in[11];
        ffn2_b  = (const float*)d_in[12];
        ln1_s   = (const float*)d_in[13];
        ln1_b   = (const float*)d_in[14];
        ln2_s   = (const float*)d_in[15];
        ln2_b   = (const float*)d_in[16];
        head_w  = (const float*)d_in[17];
        head_b  = (const float*)d_in[18];
    }
    float* out = (float*)d_out;

    float *x, *qkv, *att, *tmp, *aff, *out1, *sv, *logits_scratch, *partials;
    cudaGetSymbolAddress((void**)&x,    g_x);
    cudaGetSymbolAddress((void**)&qkv,  g_qkv);
    cudaGetSymbolAddress((void**)&att,  g_att);
    cudaGetSymbolAddress((void**)&tmp,  g_tmp);
    cudaGetSymbolAddress((void**)&aff,  g_aff);
    cudaGetSymbolAddress((void**)&out1, g_out1);
    cudaGetSymbolAddress((void**)&sv,   g_sv);
    cudaGetSymbolAddress((void**)&logits_scratch, g_logits);
    cudaGetSymbolAddress((void**)&partials, g_partials);

    const int BTV = NTOK * Vv;
    float* logits_dst = (out_size >= BTV) ? out : logits_scratch;
    float* loss_dst   = (out_size > BTV) ? (out + BTV)
                       : ((out_size > 0 && out_size < BTV) ? out : nullptr);

    const int ATTN_SMEM = 2 * TJ * DH * (int)sizeof(float);
    cudaFuncSetAttribute(attn_kernel, cudaFuncAttributeMaxDynamicSharedMemorySize, ATTN_SMEM);
    cudaFuncSetAttribute(gemm_tc_kernel, cudaFuncAttributeMaxDynamicSharedMemorySize, GEMM_SMEM_BYTES);

    detect_kernel<<<1, 1>>>((const int*)inputs);
    embed_kernel<<<NTOK, 128>>>(inputs, emb, x);

    dim3 gQKV(QKVDIM/128, NTOK/128);  // (12,32)
    dim3 gE  (Ee/128,     NTOK/128);  // (4,32)
    dim3 gHead(Vv/128,    NTOK/128);  // (1,32)
    dim3 gAtt(Bsz*Hh, Tt/64);         // (32,16)

    for (int l = 0; l < Ll; l++) {
        gemm_tc_kernel<<<gQKV, 256, GEMM_SMEM_BYTES>>>(x, qkv_w + (size_t)l*QKVDIM*Ee, qkv_b + (size_t)l*QKVDIM, qkv, QKVDIM, Ee, 0);
        svsum_kernel<<<Bsz*Hh, 512>>>(qkv, sv);
        attn_kernel<<<gAtt, 256, ATTN_SMEM>>>(qkv, sv, att);
        gemm_tc_kernel<<<gE, 256, GEMM_SMEM_BYTES>>>(att, aff1_w + (size_t)l*Ee*Ee, aff1_b + (size_t)l*Ee, tmp, Ee, Ee, 1);
        gemm_tc_kernel<<<gE, 256, GEMM_SMEM_BYTES>>>(tmp, aff2_w + (size_t)l*Ee*Ee, aff2_b + (size_t)l*Ee, aff, Ee, Ee, 0);
        add_ln_kernel<<<NTOK/8, 256>>>(aff, x, ln1_s + (size_t)l*Ee, ln1_b + (size_t)l*Ee, out1);
        gemm_tc_kernel<<<gE, 256, GEMM_SMEM_BYTES>>>(out1, ffn1_w + (size_t)l*Ee*Ee, ffn1_b + (size_t)l*Ee, tmp, Ee, Ee, 1);
        gemm_tc_kernel<<<gE, 256, GEMM_SMEM_BYTES>>>(tmp, ffn2_w + (size_t)l*Ee*Ee, ffn2_b + (size_t)l*Ee, aff, Ee, Ee, 0);
        add_ln_kernel<<<NTOK/8, 256>>>(out1, aff, ln2_s + (size_t)l*Ee, ln2_b + (size_t)l*Ee, x);
    }

    gemm_tc_kernel<<<gHead, 256, GEMM_SMEM_BYTES>>>(x, head_w, head_b, logits_dst, Vv, Ee, 0);
    loss_rows_kernel<<<NTOK/8, 256>>>(logits_dst, targets, partials);
    if (loss_dst)
        loss_final_kernel<<<1, 512>>>(partials, loss_dst);
}